// round 6
// baseline (speedup 1.0000x reference)
#include <cuda_runtime.h>
#include <cstdint>

// Problem dims (fixed by the dataset)
#define T_DIM 128
#define B_DIM 64
#define H_DIM 1024
#define M_DIM (T_DIM * B_DIM)   // 8192
#define BH    (B_DIM * H_DIM)   // 65536

// Scratch (allocation-free rule: __device__ globals)
__device__ float g_xproj[(size_t)M_DIM * H_DIM];  // 32 MB  approx x_proj
__device__ float g_spk[(size_t)M_DIM * H_DIM];    // 32 MB  spikes
__device__ int   g_cnt[B_DIM];                    // flagged count per b
__device__ int   g_list[B_DIM * H_DIM];           // flagged h list per b

#define DELTA 3e-3f

// ============================================================================
// Helpers
// ============================================================================
__device__ __forceinline__ uint32_t smem_u32(const void* p) {
    uint32_t a;
    asm("{ .reg .u64 t; cvta.to.shared.u64 t, %1; cvt.u32.u64 %0, t; }"
        : "=r"(a) : "l"(p));
    return a;
}
__device__ __forceinline__ void cp_async16(uint32_t dst, const void* src) {
    asm volatile("cp.async.cg.shared.global [%0], [%1], 16;"
                 :: "r"(dst), "l"(src) : "memory");
}
#define CP_ASYNC_COMMIT() asm volatile("cp.async.commit_group;" ::: "memory")
#define CP_ASYNC_WAIT(n)  asm volatile("cp.async.wait_group %0;" :: "n"(n) : "memory")

__device__ __forceinline__ void mma_tf32(float* d, const uint32_t* a, const uint32_t* b) {
    asm volatile(
        "mma.sync.aligned.m16n8k8.row.col.f32.tf32.tf32.f32 "
        "{%0,%1,%2,%3}, {%4,%5,%6,%7}, {%8,%9}, {%0,%1,%2,%3};"
        : "+f"(d[0]), "+f"(d[1]), "+f"(d[2]), "+f"(d[3])
        : "r"(a[0]), "r"(a[1]), "r"(a[2]), "r"(a[3]),
          "r"(b[0]), "r"(b[1]));
}

// Round an fp32 bit-pattern to a tf32 value (rna), in-register.
__device__ __forceinline__ uint32_t cvt_rna_tf32(uint32_t v) {
    uint32_t o;
    asm("cvt.rna.tf32.f32 %0, %1;" : "=r"(o) : "f"(__uint_as_float(v)));
    return o;
}

// ============================================================================
// TF32 tensor-core NT-GEMM: C[M,N] = A[M,K] * B[N,K]^T (fp32 gmem operands,
// rna-rounded to tf32 in-register at fragment load).
// CTA tile 128x128, BK=32, 512 threads (16 warps: 4(M) x 4(N), 32x32 each).
// cp.async double buffer, XOR-swizzled smem (conflict-free STS/LDS).
//   smem float index = row*32 + (((k>>2) ^ (row&7)) << 2) + (k&3)
// ============================================================================
#define BKF       32
#define TILE_U32  (128 * BKF)              // 4096 u32 = 16 KB
#define STAGE_BYTES (2 * TILE_U32 * 4)     // 32 KB
#define SMEM_DYN  (2 * STAGE_BYTES)        // 64 KB
#define NT_GEMM   512

__global__ void __launch_bounds__(NT_GEMM, 1)
gemm_tf32_mma(const float* __restrict__ A,
              const float* __restrict__ Bm,
              float* __restrict__ C)
{
    extern __shared__ float sm[];
    const uint32_t smu = smem_u32(sm);

    const int tid  = threadIdx.x;
    const int wid  = tid >> 5;
    const int lane = tid & 31;
    const int g = lane >> 2;
    const int t = lane & 3;
    const int wm = (wid >> 2) * 32;   // warp M offset (4 warps over M)
    const int wn = (wid & 3) * 32;    // warp N offset (4 warps over N)

    const int m0 = blockIdx.y * 128;
    const int n0 = blockIdx.x * 128;

    const float* Abase = A  + (size_t)m0 * H_DIM;
    const float* Bbase = Bm + (size_t)n0 * H_DIM;

    // cp.async geometry: 1024 float4 per operand tile / 512 thr = 2 each.
    int ldr[2], ldq[2];
    uint32_t sdst[2];
#pragma unroll
    for (int p = 0; p < 2; p++) {
        int f = tid + p * NT_GEMM;
        ldr[p] = f >> 3;
        ldq[p] = f & 7;
        sdst[p] = (uint32_t)((ldr[p] * 32 + ((ldq[p] ^ (ldr[p] & 7)) << 2)) * 4);
    }

    float acc[2][4][4];
#pragma unroll
    for (int i = 0; i < 2; i++)
#pragma unroll
        for (int j = 0; j < 4; j++)
#pragma unroll
            for (int r = 0; r < 4; r++) acc[i][j][r] = 0.0f;

    auto prefetch = [&](int chunk, int buf) {
        const uint32_t base = smu + (uint32_t)buf * STAGE_BYTES;
#pragma unroll
        for (int p = 0; p < 2; p++)
            cp_async16(base + sdst[p],
                       Abase + (size_t)ldr[p] * H_DIM + chunk * BKF + ldq[p] * 4);
#pragma unroll
        for (int p = 0; p < 2; p++)
            cp_async16(base + (uint32_t)TILE_U32 * 4 + sdst[p],
                       Bbase + (size_t)ldr[p] * H_DIM + chunk * BKF + ldq[p] * 4);
    };

    const int NCH = H_DIM / BKF;   // 32
    prefetch(0, 0);
    CP_ASYNC_COMMIT();

    int buf = 0;
    for (int it = 0; it < NCH; ++it) {
        if (it + 1 < NCH) {
            prefetch(it + 1, buf ^ 1);
            CP_ASYNC_COMMIT();
            CP_ASYNC_WAIT(1);
        } else {
            CP_ASYNC_WAIT(0);
        }
        __syncthreads();

        const uint32_t* As = (const uint32_t*)sm + (size_t)buf * (2 * TILE_U32);
        const uint32_t* Bs = As + TILE_U32;

#pragma unroll
        for (int ks = 0; ks < 4; ks++) {
            const int c0 = ((ks * 2) ^ g) << 2;
            const int c1 = ((ks * 2 + 1) ^ g) << 2;

            uint32_t af[2][4];
#pragma unroll
            for (int mt = 0; mt < 2; mt++) {
                const int mb = wm + mt * 16 + g;
                af[mt][0] = cvt_rna_tf32(As[mb * 32 + c0 + t]);
                af[mt][1] = cvt_rna_tf32(As[(mb + 8) * 32 + c0 + t]);
                af[mt][2] = cvt_rna_tf32(As[mb * 32 + c1 + t]);
                af[mt][3] = cvt_rna_tf32(As[(mb + 8) * 32 + c1 + t]);
            }
            uint32_t bf[4][2];
#pragma unroll
            for (int nt = 0; nt < 4; nt++) {
                const int nb = wn + nt * 8 + g;
                bf[nt][0] = cvt_rna_tf32(Bs[nb * 32 + c0 + t]);
                bf[nt][1] = cvt_rna_tf32(Bs[nb * 32 + c1 + t]);
            }
#pragma unroll
            for (int mt = 0; mt < 2; mt++)
#pragma unroll
                for (int nt = 0; nt < 4; nt++)
                    mma_tf32(acc[mt][nt], af[mt], bf[nt]);
        }
        __syncthreads();
        buf ^= 1;
    }

    // Epilogue: direct STG (float2 pairs; fragment cols 2t, 2t+1 contiguous)
#pragma unroll
    for (int mt = 0; mt < 2; mt++) {
#pragma unroll
        for (int nt = 0; nt < 4; nt++) {
            const int row = m0 + wm + mt * 16 + g;
            const int col = n0 + wn + nt * 8 + 2 * t;
            float2 v01 = make_float2(acc[mt][nt][0], acc[mt][nt][1]);
            float2 v23 = make_float2(acc[mt][nt][2], acc[mt][nt][3]);
            *(float2*)&C[(size_t)row * H_DIM + col] = v01;
            *(float2*)&C[(size_t)(row + 8) * H_DIM + col] = v23;
        }
    }
}

// ----------------------------------------------------------------------------
// LIF scan over approx x_proj + flag threshold-marginal lanes.
// ----------------------------------------------------------------------------
__global__ void __launch_bounds__(256)
scan_flag(const float* __restrict__ xp, float* __restrict__ spk,
          int* __restrict__ cnt, int* __restrict__ list)
{
    const int idx = blockIdx.x * blockDim.x + threadIdx.x;
    if (idx >= BH) return;

    float v = 0.0f;
    bool flag = false;
    #pragma unroll 4
    for (int t = 0; t < T_DIM; t++) {
        const float x = xp[(size_t)t * BH + idx];
        const float h = v + (x - v) * 0.5f;
        flag |= (fabsf(h - 1.0f) < DELTA);
        const bool fire = (h >= 1.0f);
        spk[(size_t)t * BH + idx] = fire ? 1.0f : 0.0f;
        v = fire ? 0.0f : h;
    }
    if (flag) {
        const int b = idx >> 10;
        const int h = idx & 1023;
        int p = atomicAdd(&cnt[b], 1);
        list[(b << 10) + p] = h;
    }
}

// ----------------------------------------------------------------------------
// Fixup: for flagged lanes, recompute x_proj column in EXACT sequential fp32,
// rerun LIF, overwrite spikes. Grid: (64 b, 8 slices), 256 threads.
// ----------------------------------------------------------------------------
__global__ void __launch_bounds__(256)
fixup_scan(const float* __restrict__ x,   // original fp32 x [T,B,H]
           const float* __restrict__ W1,  // original fp32 W1 [H,H]
           const int* __restrict__ cnt,
           const int* __restrict__ list,
           float* __restrict__ spk)
{
    __shared__ float Xs[128 * 65];   // 33280 B
    __shared__ float Ws[32 * 64];    //  8192 B
    __shared__ int   hlist[32];

    const int b     = blockIdx.x;
    const int slice = blockIdx.y;       // 0..7
    const int tid   = threadIdx.x;
    const int lane  = tid & 31;
    const int jb    = tid >> 5;
    const int n     = cnt[b];

    for (int base = slice * 32; base < n; base += 8 * 32) {
        const int nh = min(32, n - base);

        if (tid < 32)
            hlist[tid] = (base + tid < n) ? list[(b << 10) + base + tid] : 0;
        __syncthreads();

        float acc[4][4];
#pragma unroll
        for (int jj = 0; jj < 4; jj++)
#pragma unroll
            for (int tt = 0; tt < 4; tt++) acc[jj][tt] = 0.0f;

        for (int kc = 0; kc < 16; kc++) {
#pragma unroll
            for (int p = 0; p < 8; p++) {
                int f = tid + p * 256;
                int tt_ = f >> 4, c4 = f & 15;
                float4 v = *(const float4*)(x + (size_t)tt_ * BH + (b << 10) + kc * 64 + c4 * 4);
                float* d = &Xs[tt_ * 65 + c4 * 4];
                d[0] = v.x; d[1] = v.y; d[2] = v.z; d[3] = v.w;
            }
#pragma unroll
            for (int p = 0; p < 2; p++) {
                int f = tid + p * 256;
                int j = f >> 4, c4 = f & 15;
                float4 v = *(const float4*)(W1 + (size_t)hlist[j] * H_DIM + kc * 64 + c4 * 4);
                *(float4*)&Ws[j * 64 + c4 * 4] = v;
            }
            __syncthreads();

            for (int k = 0; k < 64; k++) {
                float wv[4], xv[4];
#pragma unroll
                for (int jj = 0; jj < 4; jj++) wv[jj] = Ws[(jb * 4 + jj) * 64 + k];
#pragma unroll
                for (int tt = 0; tt < 4; tt++) xv[tt] = Xs[(lane + tt * 32) * 65 + k];
#pragma unroll
                for (int jj = 0; jj < 4; jj++)
#pragma unroll
                    for (int tt = 0; tt < 4; tt++)
                        acc[jj][tt] = fmaf(wv[jj], xv[tt], acc[jj][tt]);
            }
            __syncthreads();
        }

        float* xcol = Xs;
#pragma unroll
        for (int jj = 0; jj < 4; jj++)
#pragma unroll
            for (int tt = 0; tt < 4; tt++)
                xcol[(jb * 4 + jj) * 129 + lane + tt * 32] = acc[jj][tt];
        __syncthreads();

        if (tid < nh) {
            const int h = hlist[tid];
            float v = 0.0f;
            for (int t = 0; t < T_DIM; t++) {
                const float xc = xcol[tid * 129 + t];
                const float hm = v + (xc - v) * 0.5f;
                const bool fire = (hm >= 1.0f);
                spk[(size_t)t * BH + (b << 10) + h] = fire ? 1.0f : 0.0f;
                v = fire ? 0.0f : hm;
            }
        }
        __syncthreads();
    }
}

// ----------------------------------------------------------------------------
// Launch
// ----------------------------------------------------------------------------
extern "C" void kernel_launch(void* const* d_in, const int* in_sizes, int n_in,
                              void* d_out, int out_size)
{
    const float* x  = (const float*)d_in[0];  // [T,B,H]
    const float* W1 = (const float*)d_in[1];  // [H,H]
    const float* W2 = (const float*)d_in[2];  // [H,H]
    float* out = (float*)d_out;               // [T,B,H]

    float *xp, *sp;
    int *cnt, *list;
    cudaGetSymbolAddress((void**)&xp, g_xproj);
    cudaGetSymbolAddress((void**)&sp, g_spk);
    cudaGetSymbolAddress((void**)&cnt, g_cnt);
    cudaGetSymbolAddress((void**)&list, g_list);

    cudaFuncSetAttribute(gemm_tf32_mma,
                         cudaFuncAttributeMaxDynamicSharedMemorySize, SMEM_DYN);

    cudaMemsetAsync(cnt, 0, B_DIM * sizeof(int));

    dim3 grid(H_DIM / 128, M_DIM / 128);  // (8, 64)

    // GEMM1 approx (tf32, in-register rna rounding): x_proj ~= x @ W1^T
    gemm_tf32_mma<<<grid, NT_GEMM, SMEM_DYN>>>(x, W1, xp);

    // LIF scan + flag marginal lanes
    scan_flag<<<BH / 256, 256>>>(xp, sp, cnt, list);

    // Exact fp32 fixup + re-scan of flagged lanes
    fixup_scan<<<dim3(B_DIM, 8), 256>>>(x, W1, cnt, list, sp);

    // GEMM2 (tf32): out = spikes @ W2^T
    gemm_tf32_mma<<<grid, NT_GEMM, SMEM_DYN>>>(sp, W2, out);
}

// round 7
// speedup vs baseline: 1.0122x; 1.0122x over previous
#include <cuda_runtime.h>
#include <cstdint>

// Problem dims (fixed by the dataset)
#define T_DIM 128
#define B_DIM 64
#define H_DIM 1024
#define M_DIM (T_DIM * B_DIM)   // 8192
#define BH    (B_DIM * H_DIM)   // 65536

// Scratch (allocation-free rule: __device__ globals)
__device__ float g_xt[(size_t)M_DIM * H_DIM];     // 32 MB  tf32-rounded x
__device__ float g_xproj[(size_t)M_DIM * H_DIM];  // 32 MB  approx x_proj
__device__ float g_spk[(size_t)M_DIM * H_DIM];    // 32 MB  spikes
__device__ float g_w1t[(size_t)H_DIM * H_DIM];    // 4 MB   tf32-rounded W1
__device__ float g_w2t[(size_t)H_DIM * H_DIM];    // 4 MB   tf32-rounded W2
__device__ int   g_cnt[B_DIM];                    // flagged count per b
__device__ int   g_list[B_DIM * H_DIM];           // flagged h list per b

#define DELTA 3e-3f

// ============================================================================
// Helpers
// ============================================================================
__device__ __forceinline__ uint32_t smem_u32(const void* p) {
    uint32_t a;
    asm("{ .reg .u64 t; cvta.to.shared.u64 t, %1; cvt.u32.u64 %0, t; }"
        : "=r"(a) : "l"(p));
    return a;
}
__device__ __forceinline__ void cp_async16(uint32_t dst, const void* src) {
    asm volatile("cp.async.cg.shared.global [%0], [%1], 16;"
                 :: "r"(dst), "l"(src) : "memory");
}
#define CP_ASYNC_COMMIT() asm volatile("cp.async.commit_group;" ::: "memory")
#define CP_ASYNC_WAIT(n)  asm volatile("cp.async.wait_group %0;" :: "n"(n) : "memory")

__device__ __forceinline__ void mma_tf32(float* d, const uint32_t* a, const uint32_t* b) {
    asm volatile(
        "mma.sync.aligned.m16n8k8.row.col.f32.tf32.tf32.f32 "
        "{%0,%1,%2,%3}, {%4,%5,%6,%7}, {%8,%9}, {%0,%1,%2,%3};"
        : "+f"(d[0]), "+f"(d[1]), "+f"(d[2]), "+f"(d[3])
        : "r"(a[0]), "r"(a[1]), "r"(a[2]), "r"(a[3]),
          "r"(b[0]), "r"(b[1]));
}

// ============================================================================
// Plain TF32 tensor-core NT-GEMM: C[M,N] = A[M,K] * B[N,K]^T (operands are
// pre-rounded tf32 values in fp32 storage).
// CTA tile 128x128, BK=32, 512 threads (16 warps: 4(M) x 4(N), 32x32 each).
// cp.async double buffer, XOR-swizzled smem (conflict-free STS/LDS).
// ============================================================================
#define BKF       32
#define TILE_U32  (128 * BKF)              // 4096 u32 = 16 KB
#define STAGE_BYTES (2 * TILE_U32 * 4)     // 32 KB
#define SMEM_DYN  (2 * STAGE_BYTES)        // 64 KB
#define NT_GEMM   512

__global__ void __launch_bounds__(NT_GEMM, 1)
gemm_tf32_mma(const float* __restrict__ A,
              const float* __restrict__ Bm,
              float* __restrict__ C)
{
    extern __shared__ float sm[];
    const uint32_t smu = smem_u32(sm);

    const int tid  = threadIdx.x;
    const int lane = tid & 31;
    const int wid  = tid >> 5;
    const int g = lane >> 2;
    const int t = lane & 3;
    const int wm = (wid >> 2) * 32;
    const int wn = (wid & 3) * 32;

    const int m0 = blockIdx.y * 128;
    const int n0 = blockIdx.x * 128;

    const float* Abase = A  + (size_t)m0 * H_DIM;
    const float* Bbase = Bm + (size_t)n0 * H_DIM;

    int ldr[2], ldq[2];
    uint32_t sdst[2];
#pragma unroll
    for (int p = 0; p < 2; p++) {
        int f = tid + p * NT_GEMM;
        ldr[p] = f >> 3;
        ldq[p] = f & 7;
        sdst[p] = (uint32_t)((ldr[p] * 32 + ((ldq[p] ^ (ldr[p] & 7)) << 2)) * 4);
    }

    float acc[2][4][4];
#pragma unroll
    for (int i = 0; i < 2; i++)
#pragma unroll
        for (int j = 0; j < 4; j++)
#pragma unroll
            for (int r = 0; r < 4; r++) acc[i][j][r] = 0.0f;

    auto prefetch = [&](int chunk, int buf) {
        const uint32_t base = smu + (uint32_t)buf * STAGE_BYTES;
#pragma unroll
        for (int p = 0; p < 2; p++)
            cp_async16(base + sdst[p],
                       Abase + (size_t)ldr[p] * H_DIM + chunk * BKF + ldq[p] * 4);
#pragma unroll
        for (int p = 0; p < 2; p++)
            cp_async16(base + (uint32_t)TILE_U32 * 4 + sdst[p],
                       Bbase + (size_t)ldr[p] * H_DIM + chunk * BKF + ldq[p] * 4);
    };

    const int NCH = H_DIM / BKF;   // 32
    prefetch(0, 0);
    CP_ASYNC_COMMIT();

    int buf = 0;
    for (int it = 0; it < NCH; ++it) {
        if (it + 1 < NCH) {
            prefetch(it + 1, buf ^ 1);
            CP_ASYNC_COMMIT();
            CP_ASYNC_WAIT(1);
        } else {
            CP_ASYNC_WAIT(0);
        }
        __syncthreads();

        const uint32_t* As = (const uint32_t*)sm + (size_t)buf * (2 * TILE_U32);
        const uint32_t* Bs = As + TILE_U32;

#pragma unroll
        for (int ks = 0; ks < 4; ks++) {
            const int c0 = ((ks * 2) ^ g) << 2;
            const int c1 = ((ks * 2 + 1) ^ g) << 2;

            uint32_t af[2][4];
#pragma unroll
            for (int mt = 0; mt < 2; mt++) {
                const int mb = wm + mt * 16 + g;
                af[mt][0] = As[mb * 32 + c0 + t];
                af[mt][1] = As[(mb + 8) * 32 + c0 + t];
                af[mt][2] = As[mb * 32 + c1 + t];
                af[mt][3] = As[(mb + 8) * 32 + c1 + t];
            }
            uint32_t bf[4][2];
#pragma unroll
            for (int nt = 0; nt < 4; nt++) {
                const int nb = wn + nt * 8 + g;
                bf[nt][0] = Bs[nb * 32 + c0 + t];
                bf[nt][1] = Bs[nb * 32 + c1 + t];
            }
#pragma unroll
            for (int mt = 0; mt < 2; mt++)
#pragma unroll
                for (int nt = 0; nt < 4; nt++)
                    mma_tf32(acc[mt][nt], af[mt], bf[nt]);
        }
        __syncthreads();
        buf ^= 1;
    }

#pragma unroll
    for (int mt = 0; mt < 2; mt++) {
#pragma unroll
        for (int nt = 0; nt < 4; nt++) {
            const int row = m0 + wm + mt * 16 + g;
            const int col = n0 + wn + nt * 8 + 2 * t;
            float2 v01 = make_float2(acc[mt][nt][0], acc[mt][nt][1]);
            float2 v23 = make_float2(acc[mt][nt][2], acc[mt][nt][3]);
            *(float2*)&C[(size_t)row * H_DIM + col] = v01;
            *(float2*)&C[(size_t)(row + 8) * H_DIM + col] = v23;
        }
    }
}

// ----------------------------------------------------------------------------
// Round fp32 array to TF32 values (rna), float4 per thread, streaming.
// ----------------------------------------------------------------------------
__global__ void __launch_bounds__(256)
round_tf32(const float* __restrict__ src, float* __restrict__ dst)
{
    int i = (blockIdx.x * blockDim.x + threadIdx.x) * 4;
    float4 v = *(const float4*)(src + i);
    uint32_t o0, o1, o2, o3;
    asm("cvt.rna.tf32.f32 %0, %1;" : "=r"(o0) : "f"(v.x));
    asm("cvt.rna.tf32.f32 %0, %1;" : "=r"(o1) : "f"(v.y));
    asm("cvt.rna.tf32.f32 %0, %1;" : "=r"(o2) : "f"(v.z));
    asm("cvt.rna.tf32.f32 %0, %1;" : "=r"(o3) : "f"(v.w));
    float4 r;
    r.x = __uint_as_float(o0); r.y = __uint_as_float(o1);
    r.z = __uint_as_float(o2); r.w = __uint_as_float(o3);
    *(float4*)(dst + i) = r;
}

// ----------------------------------------------------------------------------
// LIF scan over approx x_proj + flag threshold-marginal lanes.
// ----------------------------------------------------------------------------
__global__ void __launch_bounds__(256)
scan_flag(const float* __restrict__ xp, float* __restrict__ spk,
          int* __restrict__ cnt, int* __restrict__ list)
{
    const int idx = blockIdx.x * blockDim.x + threadIdx.x;
    if (idx >= BH) return;

    float v = 0.0f;
    bool flag = false;
    #pragma unroll 4
    for (int t = 0; t < T_DIM; t++) {
        const float x = xp[(size_t)t * BH + idx];
        const float h = v + (x - v) * 0.5f;
        flag |= (fabsf(h - 1.0f) < DELTA);
        const bool fire = (h >= 1.0f);
        spk[(size_t)t * BH + idx] = fire ? 1.0f : 0.0f;
        v = fire ? 0.0f : h;
    }
    if (flag) {
        const int b = idx >> 10;
        const int h = idx & 1023;
        int p = atomicAdd(&cnt[b], 1);
        list[(b << 10) + p] = h;
    }
}

// ----------------------------------------------------------------------------
// Fixup: recompute x_proj for flagged lanes in EXACT sequential fp32, rerun
// LIF, overwrite spikes.
// Warps partition T (warp w owns t in [16w, 16w+16)) so each Xs element is
// read by exactly one warp (8x less smem crossbar traffic than j-partition).
// Lane map: jg = lane&7 (j = jg*4+jj), tg = lane>>3 (t = w*16+tg*4+tt).
// Ws stride 65 -> banks (j+k)%32 distinct across the 8 jg lanes.
// Xs stride 65 -> banks (t+k)%32 distinct across the 4 tg groups.
// ----------------------------------------------------------------------------
__global__ void __launch_bounds__(256)
fixup_scan(const float* __restrict__ x,   // original fp32 x [T,B,H]
           const float* __restrict__ W1,  // original fp32 W1 [H,H]
           const int* __restrict__ cnt,
           const int* __restrict__ list,
           float* __restrict__ spk)
{
    __shared__ float Xs[128 * 65];   // 33280 B
    __shared__ float Ws[32 * 65];    //  8320 B
    __shared__ int   hlist[32];

    const int b     = blockIdx.x;
    const int slice = blockIdx.y;       // 0..7
    const int tid   = threadIdx.x;
    const int lane  = tid & 31;
    const int w     = tid >> 5;         // warp id -> t block
    const int jg    = lane & 7;
    const int tg    = lane >> 3;
    const int tbase = w * 16 + tg * 4;  // this thread's first t
    const int n     = cnt[b];

    for (int base = slice * 32; base < n; base += 8 * 32) {
        const int nh = min(32, n - base);

        if (tid < 32)
            hlist[tid] = (base + tid < n) ? list[(b << 10) + base + tid] : 0;
        __syncthreads();

        float acc[4][4];   // [jj][tt]
#pragma unroll
        for (int jj = 0; jj < 4; jj++)
#pragma unroll
            for (int tt = 0; tt < 4; tt++) acc[jj][tt] = 0.0f;

        for (int kc = 0; kc < 16; kc++) {
            // stage Xs: 128 t x 64 k (2048 float4 gmem, scalar STS stride 65)
#pragma unroll
            for (int p = 0; p < 8; p++) {
                int f = tid + p * 256;
                int tt_ = f >> 4, c4 = f & 15;
                float4 v = *(const float4*)(x + (size_t)tt_ * BH + (b << 10) + kc * 64 + c4 * 4);
                float* d = &Xs[tt_ * 65 + c4 * 4];
                d[0] = v.x; d[1] = v.y; d[2] = v.z; d[3] = v.w;
            }
            // stage Ws: 32 j x 64 k (scalar, stride 65)
#pragma unroll
            for (int p = 0; p < 8; p++) {
                int f = tid + p * 256;   // 0..2047
                int j = f >> 6, k = f & 63;
                Ws[j * 65 + k] = W1[(size_t)hlist[j] * H_DIM + kc * 64 + k];
            }
            __syncthreads();

            // exact fp32, thread-sequential over k
            for (int k = 0; k < 64; k++) {
                float wv[4], xv[4];
#pragma unroll
                for (int jj = 0; jj < 4; jj++) wv[jj] = Ws[(jg * 4 + jj) * 65 + k];
#pragma unroll
                for (int tt = 0; tt < 4; tt++) xv[tt] = Xs[(tbase + tt) * 65 + k];
#pragma unroll
                for (int jj = 0; jj < 4; jj++)
#pragma unroll
                    for (int tt = 0; tt < 4; tt++)
                        acc[jj][tt] = fmaf(wv[jj], xv[tt], acc[jj][tt]);
            }
            __syncthreads();
        }

        // write xcol into smem (alias Xs region): xcol[j*129 + t]
        float* xcol = Xs;
#pragma unroll
        for (int jj = 0; jj < 4; jj++)
#pragma unroll
            for (int tt = 0; tt < 4; tt++)
                xcol[(jg * 4 + jj) * 129 + tbase + tt] = acc[jj][tt];
        __syncthreads();

        // LIF rerun (threads 0..31, one per flagged h)
        if (tid < nh) {
            const int h = hlist[tid];
            float v = 0.0f;
            for (int t = 0; t < T_DIM; t++) {
                const float xc = xcol[tid * 129 + t];
                const float hm = v + (xc - v) * 0.5f;
                const bool fire = (hm >= 1.0f);
                spk[(size_t)t * BH + (b << 10) + h] = fire ? 1.0f : 0.0f;
                v = fire ? 0.0f : hm;
            }
        }
        __syncthreads();
    }
}

// ----------------------------------------------------------------------------
// Launch
// ----------------------------------------------------------------------------
extern "C" void kernel_launch(void* const* d_in, const int* in_sizes, int n_in,
                              void* d_out, int out_size)
{
    const float* x  = (const float*)d_in[0];  // [T,B,H]
    const float* W1 = (const float*)d_in[1];  // [H,H]
    const float* W2 = (const float*)d_in[2];  // [H,H]
    float* out = (float*)d_out;               // [T,B,H]

    float *xt, *xp, *sp, *w1t, *w2t;
    int *cnt, *list;
    cudaGetSymbolAddress((void**)&xt, g_xt);
    cudaGetSymbolAddress((void**)&xp, g_xproj);
    cudaGetSymbolAddress((void**)&sp, g_spk);
    cudaGetSymbolAddress((void**)&w1t, g_w1t);
    cudaGetSymbolAddress((void**)&w2t, g_w2t);
    cudaGetSymbolAddress((void**)&cnt, g_cnt);
    cudaGetSymbolAddress((void**)&list, g_list);

    cudaFuncSetAttribute(gemm_tf32_mma,
                         cudaFuncAttributeMaxDynamicSharedMemorySize, SMEM_DYN);

    cudaMemsetAsync(cnt, 0, B_DIM * sizeof(int));

    // Pre-round operands to tf32 values (rna, unbiased). Spikes are exactly
    // representable so GEMM2 needs only W2 rounded.
    round_tf32<<<(M_DIM * H_DIM) / (256 * 4), 256>>>(x, xt);
    round_tf32<<<(H_DIM * H_DIM) / (256 * 4), 256>>>(W1, w1t);
    round_tf32<<<(H_DIM * H_DIM) / (256 * 4), 256>>>(W2, w2t);

    dim3 grid(H_DIM / 128, M_DIM / 128);  // (8, 64)

    // GEMM1 approx (tf32): x_proj ~= x @ W1^T
    gemm_tf32_mma<<<grid, NT_GEMM, SMEM_DYN>>>(xt, w1t, xp);

    // LIF scan + flag marginal lanes
    scan_flag<<<BH / 256, 256>>>(xp, sp, cnt, list);

    // Exact fp32 fixup + re-scan of flagged lanes
    fixup_scan<<<dim3(B_DIM, 8), 256>>>(x, W1, cnt, list, sp);

    // GEMM2 (tf32): out = spikes @ W2^T
    gemm_tf32_mma<<<grid, NT_GEMM, SMEM_DYN>>>(sp, w2t, out);
}

// round 8
// speedup vs baseline: 1.2460x; 1.2310x over previous
#include <cuda_runtime.h>
#include <cstdint>

// Problem dims (fixed by the dataset)
#define T_DIM 128
#define B_DIM 64
#define H_DIM 1024
#define M_DIM (T_DIM * B_DIM)   // 8192
#define BH    (B_DIM * H_DIM)   // 65536

// Scratch (allocation-free rule: __device__ globals)
__device__ float g_xt[(size_t)M_DIM * H_DIM];     // 32 MB  tf32-rounded x
__device__ float g_xproj[(size_t)M_DIM * H_DIM];  // 32 MB  approx x_proj
__device__ float g_spk[(size_t)M_DIM * H_DIM];    // 32 MB  spikes
__device__ float g_w1t[(size_t)H_DIM * H_DIM];    // 4 MB   tf32-rounded W1
__device__ float g_w2t[(size_t)H_DIM * H_DIM];    // 4 MB   tf32-rounded W2
__device__ int   g_cnt[B_DIM];                    // flagged count per b
__device__ int   g_list[B_DIM * H_DIM];           // flagged h list per b

#define DELTA 1e-3f

// ============================================================================
// Helpers
// ============================================================================
__device__ __forceinline__ uint32_t smem_u32(const void* p) {
    uint32_t a;
    asm("{ .reg .u64 t; cvta.to.shared.u64 t, %1; cvt.u32.u64 %0, t; }"
        : "=r"(a) : "l"(p));
    return a;
}
__device__ __forceinline__ void cp_async16(uint32_t dst, const void* src) {
    asm volatile("cp.async.cg.shared.global [%0], [%1], 16;"
                 :: "r"(dst), "l"(src) : "memory");
}
#define CP_ASYNC_COMMIT() asm volatile("cp.async.commit_group;" ::: "memory")
#define CP_ASYNC_WAIT(n)  asm volatile("cp.async.wait_group %0;" :: "n"(n) : "memory")

__device__ __forceinline__ void mma_tf32(float* d, const uint32_t* a, const uint32_t* b) {
    asm volatile(
        "mma.sync.aligned.m16n8k8.row.col.f32.tf32.tf32.f32 "
        "{%0,%1,%2,%3}, {%4,%5,%6,%7}, {%8,%9}, {%0,%1,%2,%3};"
        : "+f"(d[0]), "+f"(d[1]), "+f"(d[2]), "+f"(d[3])
        : "r"(a[0]), "r"(a[1]), "r"(a[2]), "r"(a[3]),
          "r"(b[0]), "r"(b[1]));
}

// ============================================================================
// Plain TF32 tensor-core NT-GEMM: C[M,N] = A[M,K] * B[N,K]^T (operands are
// pre-rounded tf32 values in fp32 storage).
// CTA tile 256x128, BK=32, 256 threads (8 warps: 4(M) x 2(N), 64x64 each).
// LDS/MMA = 1.0 (32 scalar LDS per 32 MMAs per ks-step).
// cp.async double buffer, XOR-swizzled smem (conflict-free STS/LDS):
//   smem float index = row*32 + (((k>>2) ^ (row&7)) << 2) + (k&3)
// ============================================================================
#define BM        256
#define BN        128
#define BKF       32
#define A_U32     (BM * BKF)               // 8192 u32 = 32 KB
#define B_U32     (BN * BKF)               // 4096 u32 = 16 KB
#define STAGE_U32 (A_U32 + B_U32)          // 12288 u32 = 48 KB
#define STAGE_BYTES (STAGE_U32 * 4)
#define SMEM_DYN  (2 * STAGE_BYTES)        // 96 KB
#define NT_GEMM   256

__global__ void __launch_bounds__(NT_GEMM, 1)
gemm_tf32_mma(const float* __restrict__ A,
              const float* __restrict__ Bm,
              float* __restrict__ C)
{
    extern __shared__ float sm[];
    const uint32_t smu = smem_u32(sm);

    const int tid  = threadIdx.x;
    const int lane = tid & 31;
    const int wid  = tid >> 5;
    const int g = lane >> 2;
    const int t = lane & 3;
    const int wm = (wid >> 1) * 64;   // 4 warps over M
    const int wn = (wid & 1) * 64;    // 2 warps over N

    const int m0 = blockIdx.y * BM;
    const int n0 = blockIdx.x * BN;

    const float* Abase = A  + (size_t)m0 * H_DIM;
    const float* Bbase = Bm + (size_t)n0 * H_DIM;

    // cp.async geometry: A = 2048 f4 / 256 thr = 8; B = 1024 / 256 = 4.
    int lra[8], lqa[8];
    uint32_t sda[8];
#pragma unroll
    for (int p = 0; p < 8; p++) {
        int f = tid + p * 256;
        lra[p] = f >> 3;
        lqa[p] = f & 7;
        sda[p] = (uint32_t)((lra[p] * 32 + ((lqa[p] ^ (lra[p] & 7)) << 2)) * 4);
    }
    int lrb[4], lqb[4];
    uint32_t sdb[4];
#pragma unroll
    for (int p = 0; p < 4; p++) {
        int f = tid + p * 256;
        lrb[p] = f >> 3;
        lqb[p] = f & 7;
        sdb[p] = (uint32_t)((lrb[p] * 32 + ((lqb[p] ^ (lrb[p] & 7)) << 2)) * 4);
    }

    float acc[4][8][4];
#pragma unroll
    for (int i = 0; i < 4; i++)
#pragma unroll
        for (int j = 0; j < 8; j++)
#pragma unroll
            for (int r = 0; r < 4; r++) acc[i][j][r] = 0.0f;

    auto prefetch = [&](int chunk, int buf) {
        const uint32_t base = smu + (uint32_t)buf * STAGE_BYTES;
#pragma unroll
        for (int p = 0; p < 8; p++)
            cp_async16(base + sda[p],
                       Abase + (size_t)lra[p] * H_DIM + chunk * BKF + lqa[p] * 4);
#pragma unroll
        for (int p = 0; p < 4; p++)
            cp_async16(base + (uint32_t)(A_U32 * 4) + sdb[p],
                       Bbase + (size_t)lrb[p] * H_DIM + chunk * BKF + lqb[p] * 4);
    };

    const int NCH = H_DIM / BKF;   // 32
    prefetch(0, 0);
    CP_ASYNC_COMMIT();

    int buf = 0;
    for (int it = 0; it < NCH; ++it) {
        if (it + 1 < NCH) {
            prefetch(it + 1, buf ^ 1);
            CP_ASYNC_COMMIT();
            CP_ASYNC_WAIT(1);
        } else {
            CP_ASYNC_WAIT(0);
        }
        __syncthreads();

        const uint32_t* As = (const uint32_t*)sm + (size_t)buf * STAGE_U32;
        const uint32_t* Bs = As + A_U32;

#pragma unroll
        for (int ks = 0; ks < 4; ks++) {
            const int c0 = ((ks * 2) ^ g) << 2;
            const int c1 = ((ks * 2 + 1) ^ g) << 2;

            uint32_t af[4][4];
#pragma unroll
            for (int mt = 0; mt < 4; mt++) {
                const int mb = wm + mt * 16 + g;
                af[mt][0] = As[mb * 32 + c0 + t];
                af[mt][1] = As[(mb + 8) * 32 + c0 + t];
                af[mt][2] = As[mb * 32 + c1 + t];
                af[mt][3] = As[(mb + 8) * 32 + c1 + t];
            }
            uint32_t bf[8][2];
#pragma unroll
            for (int nt = 0; nt < 8; nt++) {
                const int nb = wn + nt * 8 + g;
                bf[nt][0] = Bs[nb * 32 + c0 + t];
                bf[nt][1] = Bs[nb * 32 + c1 + t];
            }
#pragma unroll
            for (int mt = 0; mt < 4; mt++)
#pragma unroll
                for (int nt = 0; nt < 8; nt++)
                    mma_tf32(acc[mt][nt], af[mt], bf[nt]);
        }
        __syncthreads();
        buf ^= 1;
    }

    // Epilogue: direct STG (float2 pairs; fragment cols 2t, 2t+1 contiguous)
#pragma unroll
    for (int mt = 0; mt < 4; mt++) {
#pragma unroll
        for (int nt = 0; nt < 8; nt++) {
            const int row = m0 + wm + mt * 16 + g;
            const int col = n0 + wn + nt * 8 + 2 * t;
            float2 v01 = make_float2(acc[mt][nt][0], acc[mt][nt][1]);
            float2 v23 = make_float2(acc[mt][nt][2], acc[mt][nt][3]);
            *(float2*)&C[(size_t)row * H_DIM + col] = v01;
            *(float2*)&C[(size_t)(row + 8) * H_DIM + col] = v23;
        }
    }
}

// ----------------------------------------------------------------------------
// Round fp32 array to TF32 values (rna), float4 per thread, streaming.
// ----------------------------------------------------------------------------
__global__ void __launch_bounds__(256)
round_tf32(const float* __restrict__ src, float* __restrict__ dst)
{
    int i = (blockIdx.x * blockDim.x + threadIdx.x) * 4;
    float4 v = *(const float4*)(src + i);
    uint32_t o0, o1, o2, o3;
    asm("cvt.rna.tf32.f32 %0, %1;" : "=r"(o0) : "f"(v.x));
    asm("cvt.rna.tf32.f32 %0, %1;" : "=r"(o1) : "f"(v.y));
    asm("cvt.rna.tf32.f32 %0, %1;" : "=r"(o2) : "f"(v.z));
    asm("cvt.rna.tf32.f32 %0, %1;" : "=r"(o3) : "f"(v.w));
    float4 r;
    r.x = __uint_as_float(o0); r.y = __uint_as_float(o1);
    r.z = __uint_as_float(o2); r.w = __uint_as_float(o3);
    *(float4*)(dst + i) = r;
}

// ----------------------------------------------------------------------------
// LIF scan over approx x_proj + flag threshold-marginal lanes.
// ----------------------------------------------------------------------------
__global__ void __launch_bounds__(256)
scan_flag(const float* __restrict__ xp, float* __restrict__ spk,
          int* __restrict__ cnt, int* __restrict__ list)
{
    const int idx = blockIdx.x * blockDim.x + threadIdx.x;
    if (idx >= BH) return;

    float v = 0.0f;
    bool flag = false;
    #pragma unroll 4
    for (int t = 0; t < T_DIM; t++) {
        const float x = xp[(size_t)t * BH + idx];
        const float h = v + (x - v) * 0.5f;
        flag |= (fabsf(h - 1.0f) < DELTA);
        const bool fire = (h >= 1.0f);
        spk[(size_t)t * BH + idx] = fire ? 1.0f : 0.0f;
        v = fire ? 0.0f : h;
    }
    if (flag) {
        const int b = idx >> 10;
        const int h = idx & 1023;
        int p = atomicAdd(&cnt[b], 1);
        list[(b << 10) + p] = h;
    }
}

// ----------------------------------------------------------------------------
// Fixup: recompute x_proj for flagged lanes in EXACT sequential fp32, rerun
// LIF, overwrite spikes. Grid (B_DIM, 2).
// Warps partition T; lane map jg = lane&7 (j = jg*4+jj), tg = lane>>3.
// ----------------------------------------------------------------------------
#define FIX_SLICES 2

__global__ void __launch_bounds__(256)
fixup_scan(const float* __restrict__ x,   // original fp32 x [T,B,H]
           const float* __restrict__ W1,  // original fp32 W1 [H,H]
           const int* __restrict__ cnt,
           const int* __restrict__ list,
           float* __restrict__ spk)
{
    __shared__ float Xs[128 * 65];   // 33280 B
    __shared__ float Ws[32 * 65];    //  8320 B
    __shared__ int   hlist[32];

    const int b     = blockIdx.x;
    const int slice = blockIdx.y;
    const int tid   = threadIdx.x;
    const int lane  = tid & 31;
    const int w     = tid >> 5;
    const int jg    = lane & 7;
    const int tg    = lane >> 3;
    const int tbase = w * 16 + tg * 4;
    const int n     = cnt[b];

    for (int base = slice * 32; base < n; base += FIX_SLICES * 32) {
        const int nh = min(32, n - base);

        if (tid < 32)
            hlist[tid] = (base + tid < n) ? list[(b << 10) + base + tid] : 0;
        __syncthreads();

        float acc[4][4];   // [jj][tt]
#pragma unroll
        for (int jj = 0; jj < 4; jj++)
#pragma unroll
            for (int tt = 0; tt < 4; tt++) acc[jj][tt] = 0.0f;

        for (int kc = 0; kc < 16; kc++) {
#pragma unroll
            for (int p = 0; p < 8; p++) {
                int f = tid + p * 256;
                int tt_ = f >> 4, c4 = f & 15;
                float4 v = *(const float4*)(x + (size_t)tt_ * BH + (b << 10) + kc * 64 + c4 * 4);
                float* d = &Xs[tt_ * 65 + c4 * 4];
                d[0] = v.x; d[1] = v.y; d[2] = v.z; d[3] = v.w;
            }
#pragma unroll
            for (int p = 0; p < 8; p++) {
                int f = tid + p * 256;
                int j = f >> 6, k = f & 63;
                Ws[j * 65 + k] = W1[(size_t)hlist[j] * H_DIM + kc * 64 + k];
            }
            __syncthreads();

            for (int k = 0; k < 64; k++) {
                float wv[4], xv[4];
#pragma unroll
                for (int jj = 0; jj < 4; jj++) wv[jj] = Ws[(jg * 4 + jj) * 65 + k];
#pragma unroll
                for (int tt = 0; tt < 4; tt++) xv[tt] = Xs[(tbase + tt) * 65 + k];
#pragma unroll
                for (int jj = 0; jj < 4; jj++)
#pragma unroll
                    for (int tt = 0; tt < 4; tt++)
                        acc[jj][tt] = fmaf(wv[jj], xv[tt], acc[jj][tt]);
            }
            __syncthreads();
        }

        float* xcol = Xs;
#pragma unroll
        for (int jj = 0; jj < 4; jj++)
#pragma unroll
            for (int tt = 0; tt < 4; tt++)
                xcol[(jg * 4 + jj) * 129 + tbase + tt] = acc[jj][tt];
        __syncthreads();

        if (tid < nh) {
            const int h = hlist[tid];
            float v = 0.0f;
            for (int t = 0; t < T_DIM; t++) {
                const float xc = xcol[tid * 129 + t];
                const float hm = v + (xc - v) * 0.5f;
                const bool fire = (hm >= 1.0f);
                spk[(size_t)t * BH + (b << 10) + h] = fire ? 1.0f : 0.0f;
                v = fire ? 0.0f : hm;
            }
        }
        __syncthreads();
    }
}

// ----------------------------------------------------------------------------
// Launch
// ----------------------------------------------------------------------------
extern "C" void kernel_launch(void* const* d_in, const int* in_sizes, int n_in,
                              void* d_out, int out_size)
{
    const float* x  = (const float*)d_in[0];  // [T,B,H]
    const float* W1 = (const float*)d_in[1];  // [H,H]
    const float* W2 = (const float*)d_in[2];  // [H,H]
    float* out = (float*)d_out;               // [T,B,H]

    float *xt, *xp, *sp, *w1t, *w2t;
    int *cnt, *list;
    cudaGetSymbolAddress((void**)&xt, g_xt);
    cudaGetSymbolAddress((void**)&xp, g_xproj);
    cudaGetSymbolAddress((void**)&sp, g_spk);
    cudaGetSymbolAddress((void**)&w1t, g_w1t);
    cudaGetSymbolAddress((void**)&w2t, g_w2t);
    cudaGetSymbolAddress((void**)&cnt, g_cnt);
    cudaGetSymbolAddress((void**)&list, g_list);

    cudaFuncSetAttribute(gemm_tf32_mma,
                         cudaFuncAttributeMaxDynamicSharedMemorySize, SMEM_DYN);

    cudaMemsetAsync(cnt, 0, B_DIM * sizeof(int));

    // Pre-round operands to tf32 values (rna, unbiased). Spikes are exactly
    // representable so GEMM2 needs only W2 rounded.
    round_tf32<<<(M_DIM * H_DIM) / (256 * 4), 256>>>(x, xt);
    round_tf32<<<(H_DIM * H_DIM) / (256 * 4), 256>>>(W1, w1t);
    round_tf32<<<(H_DIM * H_DIM) / (256 * 4), 256>>>(W2, w2t);

    dim3 grid(H_DIM / BN, M_DIM / BM);  // (8, 32)

    // GEMM1 approx (tf32): x_proj ~= x @ W1^T
    gemm_tf32_mma<<<grid, NT_GEMM, SMEM_DYN>>>(xt, w1t, xp);

    // LIF scan + flag marginal lanes
    scan_flag<<<BH / 256, 256>>>(xp, sp, cnt, list);

    // Exact fp32 fixup + re-scan of flagged lanes
    fixup_scan<<<dim3(B_DIM, FIX_SLICES), 256>>>(x, W1, cnt, list, sp);

    // GEMM2 (tf32): out = spikes @ W2^T
    gemm_tf32_mma<<<grid, NT_GEMM, SMEM_DYN>>>(sp, w2t, out);
}

// round 9
// speedup vs baseline: 1.2541x; 1.0065x over previous
#include <cuda_runtime.h>
#include <cstdint>

// Problem dims (fixed by the dataset)
#define T_DIM 128
#define B_DIM 64
#define H_DIM 1024
#define M_DIM (T_DIM * B_DIM)   // 8192
#define BH    (B_DIM * H_DIM)   // 65536

// Scratch (allocation-free rule: __device__ globals)
__device__ float g_xt[(size_t)M_DIM * H_DIM];     // 32 MB  tf32-rounded x
__device__ float g_xproj[(size_t)M_DIM * H_DIM];  // 32 MB  approx x_proj
__device__ float g_spk[(size_t)M_DIM * H_DIM];    // 32 MB  spikes
__device__ float g_w1t[(size_t)H_DIM * H_DIM];    // 4 MB   tf32-rounded W1
__device__ float g_w2t[(size_t)H_DIM * H_DIM];    // 4 MB   tf32-rounded W2
__device__ int   g_cnt[B_DIM];                    // flagged count per b
__device__ int   g_list[B_DIM * H_DIM];           // flagged h list per b

#define DELTA 1e-3f

// ============================================================================
// Helpers
// ============================================================================
__device__ __forceinline__ uint32_t smem_u32(const void* p) {
    uint32_t a;
    asm("{ .reg .u64 t; cvta.to.shared.u64 t, %1; cvt.u32.u64 %0, t; }"
        : "=r"(a) : "l"(p));
    return a;
}
__device__ __forceinline__ void cp_async16(uint32_t dst, const void* src) {
    asm volatile("cp.async.cg.shared.global [%0], [%1], 16;"
                 :: "r"(dst), "l"(src) : "memory");
}
#define CP_ASYNC_COMMIT() asm volatile("cp.async.commit_group;" ::: "memory")
#define CP_ASYNC_WAIT(n)  asm volatile("cp.async.wait_group %0;" :: "n"(n) : "memory")

__device__ __forceinline__ void mma_tf32(float* d, const uint32_t* a, const uint32_t* b) {
    asm volatile(
        "mma.sync.aligned.m16n8k8.row.col.f32.tf32.tf32.f32 "
        "{%0,%1,%2,%3}, {%4,%5,%6,%7}, {%8,%9}, {%0,%1,%2,%3};"
        : "+f"(d[0]), "+f"(d[1]), "+f"(d[2]), "+f"(d[3])
        : "r"(a[0]), "r"(a[1]), "r"(a[2]), "r"(a[3]),
          "r"(b[0]), "r"(b[1]));
}

// ============================================================================
// Plain TF32 tensor-core NT-GEMM: C[M,N] = A[M,K] * B[N,K]^T (operands are
// pre-rounded tf32 values in fp32 storage).
// CTA tile 256x128, BK=32, 256 threads (8 warps: 4(M) x 2(N), 64x64 each).
// 3-stage cp.async pipeline, ONE __syncthreads per chunk:
//   wait(chunk i landed) -> barrier (all reads of chunk i-1 done)
//   -> prefetch chunk i+2 into stage (i+2)%3 (== (i-1)%3) -> compute chunk i.
// XOR-swizzled smem: float index = row*32 + (((k>>2) ^ (row&7)) << 2) + (k&3)
// ============================================================================
#define BM        256
#define BN        128
#define BKF       32
#define A_U32     (BM * BKF)               // 8192 u32 = 32 KB
#define B_U32     (BN * BKF)               // 4096 u32 = 16 KB
#define STAGE_U32 (A_U32 + B_U32)          // 12288 u32 = 48 KB
#define STAGE_BYTES (STAGE_U32 * 4)
#define NSTAGE    3
#define SMEM_DYN  (NSTAGE * STAGE_BYTES)   // 144 KB
#define NT_GEMM   256

__global__ void __launch_bounds__(NT_GEMM, 1)
gemm_tf32_mma(const float* __restrict__ A,
              const float* __restrict__ Bm,
              float* __restrict__ C)
{
    extern __shared__ float sm[];
    const uint32_t smu = smem_u32(sm);

    const int tid  = threadIdx.x;
    const int lane = tid & 31;
    const int wid  = tid >> 5;
    const int g = lane >> 2;
    const int t = lane & 3;
    const int wm = (wid >> 1) * 64;   // 4 warps over M
    const int wn = (wid & 1) * 64;    // 2 warps over N

    const int m0 = blockIdx.y * BM;
    const int n0 = blockIdx.x * BN;

    const float* Abase = A  + (size_t)m0 * H_DIM;
    const float* Bbase = Bm + (size_t)n0 * H_DIM;

    // cp.async geometry: A = 2048 f4 / 256 thr = 8; B = 1024 / 256 = 4.
    int lra[8], lqa[8];
    uint32_t sda[8];
#pragma unroll
    for (int p = 0; p < 8; p++) {
        int f = tid + p * 256;
        lra[p] = f >> 3;
        lqa[p] = f & 7;
        sda[p] = (uint32_t)((lra[p] * 32 + ((lqa[p] ^ (lra[p] & 7)) << 2)) * 4);
    }
    int lrb[4], lqb[4];
    uint32_t sdb[4];
#pragma unroll
    for (int p = 0; p < 4; p++) {
        int f = tid + p * 256;
        lrb[p] = f >> 3;
        lqb[p] = f & 7;
        sdb[p] = (uint32_t)((lrb[p] * 32 + ((lqb[p] ^ (lrb[p] & 7)) << 2)) * 4);
    }

    float acc[4][8][4];
#pragma unroll
    for (int i = 0; i < 4; i++)
#pragma unroll
        for (int j = 0; j < 8; j++)
#pragma unroll
            for (int r = 0; r < 4; r++) acc[i][j][r] = 0.0f;

    auto prefetch = [&](int chunk, int stage) {
        const uint32_t base = smu + (uint32_t)stage * STAGE_BYTES;
#pragma unroll
        for (int p = 0; p < 8; p++)
            cp_async16(base + sda[p],
                       Abase + (size_t)lra[p] * H_DIM + chunk * BKF + lqa[p] * 4);
#pragma unroll
        for (int p = 0; p < 4; p++)
            cp_async16(base + (uint32_t)(A_U32 * 4) + sdb[p],
                       Bbase + (size_t)lrb[p] * H_DIM + chunk * BKF + lqb[p] * 4);
    };

    const int NCH = H_DIM / BKF;   // 32
    prefetch(0, 0);
    CP_ASYNC_COMMIT();
    prefetch(1, 1);
    CP_ASYNC_COMMIT();

    int stage = 0;
    for (int it = 0; it < NCH; ++it) {
        // Ensure chunk `it` has landed (groups complete in order; allowing one
        // pending group leaves only chunk it+1 outstanding).
        if (it + 1 < NCH) { CP_ASYNC_WAIT(1); } else { CP_ASYNC_WAIT(0); }
        // All warps finished reading chunk it-1 (stage (it-1)%3) after this.
        __syncthreads();
        // Refill the just-freed stage with chunk it+2.
        if (it + 2 < NCH) {
            int s2 = stage + 2; if (s2 >= NSTAGE) s2 -= NSTAGE;
            prefetch(it + 2, s2);
            CP_ASYNC_COMMIT();
        }

        const uint32_t* As = (const uint32_t*)sm + (size_t)stage * STAGE_U32;
        const uint32_t* Bs = As + A_U32;

#pragma unroll
        for (int ks = 0; ks < 4; ks++) {
            const int c0 = ((ks * 2) ^ g) << 2;
            const int c1 = ((ks * 2 + 1) ^ g) << 2;

            uint32_t af[4][4];
#pragma unroll
            for (int mt = 0; mt < 4; mt++) {
                const int mb = wm + mt * 16 + g;
                af[mt][0] = As[mb * 32 + c0 + t];
                af[mt][1] = As[(mb + 8) * 32 + c0 + t];
                af[mt][2] = As[mb * 32 + c1 + t];
                af[mt][3] = As[(mb + 8) * 32 + c1 + t];
            }
            uint32_t bf[8][2];
#pragma unroll
            for (int nt = 0; nt < 8; nt++) {
                const int nb = wn + nt * 8 + g;
                bf[nt][0] = Bs[nb * 32 + c0 + t];
                bf[nt][1] = Bs[nb * 32 + c1 + t];
            }
#pragma unroll
            for (int mt = 0; mt < 4; mt++)
#pragma unroll
                for (int nt = 0; nt < 8; nt++)
                    mma_tf32(acc[mt][nt], af[mt], bf[nt]);
        }

        if (++stage >= NSTAGE) stage = 0;
    }

    // Epilogue: direct STG (float2 pairs; fragment cols 2t, 2t+1 contiguous)
#pragma unroll
    for (int mt = 0; mt < 4; mt++) {
#pragma unroll
        for (int nt = 0; nt < 8; nt++) {
            const int row = m0 + wm + mt * 16 + g;
            const int col = n0 + wn + nt * 8 + 2 * t;
            float2 v01 = make_float2(acc[mt][nt][0], acc[mt][nt][1]);
            float2 v23 = make_float2(acc[mt][nt][2], acc[mt][nt][3]);
            *(float2*)&C[(size_t)row * H_DIM + col] = v01;
            *(float2*)&C[(size_t)(row + 8) * H_DIM + col] = v23;
        }
    }
}

// ----------------------------------------------------------------------------
// Round fp32 array to TF32 values (rna), float4 per thread, streaming.
// Also zeroes the flag counters from block 0 (saves a memset launch).
// ----------------------------------------------------------------------------
__global__ void __launch_bounds__(256)
round_tf32(const float* __restrict__ src, float* __restrict__ dst,
           int* __restrict__ cnt_to_zero)
{
    if (cnt_to_zero && blockIdx.x == 0 && threadIdx.x < B_DIM)
        cnt_to_zero[threadIdx.x] = 0;

    int i = (blockIdx.x * blockDim.x + threadIdx.x) * 4;
    float4 v = *(const float4*)(src + i);
    uint32_t o0, o1, o2, o3;
    asm("cvt.rna.tf32.f32 %0, %1;" : "=r"(o0) : "f"(v.x));
    asm("cvt.rna.tf32.f32 %0, %1;" : "=r"(o1) : "f"(v.y));
    asm("cvt.rna.tf32.f32 %0, %1;" : "=r"(o2) : "f"(v.z));
    asm("cvt.rna.tf32.f32 %0, %1;" : "=r"(o3) : "f"(v.w));
    float4 r;
    r.x = __uint_as_float(o0); r.y = __uint_as_float(o1);
    r.z = __uint_as_float(o2); r.w = __uint_as_float(o3);
    *(float4*)(dst + i) = r;
}

// ----------------------------------------------------------------------------
// LIF scan over approx x_proj + flag threshold-marginal lanes.
// ----------------------------------------------------------------------------
__global__ void __launch_bounds__(256)
scan_flag(const float* __restrict__ xp, float* __restrict__ spk,
          int* __restrict__ cnt, int* __restrict__ list)
{
    const int idx = blockIdx.x * blockDim.x + threadIdx.x;
    if (idx >= BH) return;

    float v = 0.0f;
    bool flag = false;
    #pragma unroll 8
    for (int t = 0; t < T_DIM; t++) {
        const float x = xp[(size_t)t * BH + idx];
        const float h = v + (x - v) * 0.5f;
        flag |= (fabsf(h - 1.0f) < DELTA);
        const bool fire = (h >= 1.0f);
        spk[(size_t)t * BH + idx] = fire ? 1.0f : 0.0f;
        v = fire ? 0.0f : h;
    }
    if (flag) {
        const int b = idx >> 10;
        const int h = idx & 1023;
        int p = atomicAdd(&cnt[b], 1);
        list[(b << 10) + p] = h;
    }
}

// ----------------------------------------------------------------------------
// Fixup: recompute x_proj for flagged lanes in EXACT sequential fp32, rerun
// LIF, overwrite spikes. Grid (B_DIM, FIX_SLICES).
// Warps partition T; lane map jg = lane&7 (j = jg*4+jj), tg = lane>>3.
// ----------------------------------------------------------------------------
#define FIX_SLICES 2

__global__ void __launch_bounds__(256)
fixup_scan(const float* __restrict__ x,   // original fp32 x [T,B,H]
           const float* __restrict__ W1,  // original fp32 W1 [H,H]
           const int* __restrict__ cnt,
           const int* __restrict__ list,
           float* __restrict__ spk)
{
    __shared__ float Xs[128 * 65];   // 33280 B
    __shared__ float Ws[32 * 65];    //  8320 B
    __shared__ int   hlist[32];

    const int b     = blockIdx.x;
    const int slice = blockIdx.y;
    const int tid   = threadIdx.x;
    const int lane  = tid & 31;
    const int w     = tid >> 5;
    const int jg    = lane & 7;
    const int tg    = lane >> 3;
    const int tbase = w * 16 + tg * 4;
    const int n     = cnt[b];

    for (int base = slice * 32; base < n; base += FIX_SLICES * 32) {
        const int nh = min(32, n - base);

        if (tid < 32)
            hlist[tid] = (base + tid < n) ? list[(b << 10) + base + tid] : 0;
        __syncthreads();

        float acc[4][4];   // [jj][tt]
#pragma unroll
        for (int jj = 0; jj < 4; jj++)
#pragma unroll
            for (int tt = 0; tt < 4; tt++) acc[jj][tt] = 0.0f;

        for (int kc = 0; kc < 16; kc++) {
#pragma unroll
            for (int p = 0; p < 8; p++) {
                int f = tid + p * 256;
                int tt_ = f >> 4, c4 = f & 15;
                float4 v = *(const float4*)(x + (size_t)tt_ * BH + (b << 10) + kc * 64 + c4 * 4);
                float* d = &Xs[tt_ * 65 + c4 * 4];
                d[0] = v.x; d[1] = v.y; d[2] = v.z; d[3] = v.w;
            }
#pragma unroll
            for (int p = 0; p < 8; p++) {
                int f = tid + p * 256;
                int j = f >> 6, k = f & 63;
                Ws[j * 65 + k] = W1[(size_t)hlist[j] * H_DIM + kc * 64 + k];
            }
            __syncthreads();

            for (int k = 0; k < 64; k++) {
                float wv[4], xv[4];
#pragma unroll
                for (int jj = 0; jj < 4; jj++) wv[jj] = Ws[(jg * 4 + jj) * 65 + k];
#pragma unroll
                for (int tt = 0; tt < 4; tt++) xv[tt] = Xs[(tbase + tt) * 65 + k];
#pragma unroll
                for (int jj = 0; jj < 4; jj++)
#pragma unroll
                    for (int tt = 0; tt < 4; tt++)
                        acc[jj][tt] = fmaf(wv[jj], xv[tt], acc[jj][tt]);
            }
            __syncthreads();
        }

        float* xcol = Xs;
#pragma unroll
        for (int jj = 0; jj < 4; jj++)
#pragma unroll
            for (int tt = 0; tt < 4; tt++)
                xcol[(jg * 4 + jj) * 129 + tbase + tt] = acc[jj][tt];
        __syncthreads();

        if (tid < nh) {
            const int h = hlist[tid];
            float v = 0.0f;
            for (int t = 0; t < T_DIM; t++) {
                const float xc = xcol[tid * 129 + t];
                const float hm = v + (xc - v) * 0.5f;
                const bool fire = (hm >= 1.0f);
                spk[(size_t)t * BH + (b << 10) + h] = fire ? 1.0f : 0.0f;
                v = fire ? 0.0f : hm;
            }
        }
        __syncthreads();
    }
}

// ----------------------------------------------------------------------------
// Launch
// ----------------------------------------------------------------------------
extern "C" void kernel_launch(void* const* d_in, const int* in_sizes, int n_in,
                              void* d_out, int out_size)
{
    const float* x  = (const float*)d_in[0];  // [T,B,H]
    const float* W1 = (const float*)d_in[1];  // [H,H]
    const float* W2 = (const float*)d_in[2];  // [H,H]
    float* out = (float*)d_out;               // [T,B,H]

    float *xt, *xp, *sp, *w1t, *w2t;
    int *cnt, *list;
    cudaGetSymbolAddress((void**)&xt, g_xt);
    cudaGetSymbolAddress((void**)&xp, g_xproj);
    cudaGetSymbolAddress((void**)&sp, g_spk);
    cudaGetSymbolAddress((void**)&w1t, g_w1t);
    cudaGetSymbolAddress((void**)&w2t, g_w2t);
    cudaGetSymbolAddress((void**)&cnt, g_cnt);
    cudaGetSymbolAddress((void**)&list, g_list);

    cudaFuncSetAttribute(gemm_tf32_mma,
                         cudaFuncAttributeMaxDynamicSharedMemorySize, SMEM_DYN);

    // Pre-round operands to tf32 values (rna, unbiased). Spikes are exactly
    // representable so GEMM2 needs only W2 rounded. First round also zeroes cnt.
    round_tf32<<<(M_DIM * H_DIM) / (256 * 4), 256>>>(x, xt, cnt);
    round_tf32<<<(H_DIM * H_DIM) / (256 * 4), 256>>>(W1, w1t, nullptr);
    round_tf32<<<(H_DIM * H_DIM) / (256 * 4), 256>>>(W2, w2t, nullptr);

    dim3 grid(H_DIM / BN, M_DIM / BM);  // (8, 32)

    // GEMM1 approx (tf32): x_proj ~= x @ W1^T
    gemm_tf32_mma<<<grid, NT_GEMM, SMEM_DYN>>>(xt, w1t, xp);

    // LIF scan + flag marginal lanes
    scan_flag<<<BH / 256, 256>>>(xp, sp, cnt, list);

    // Exact fp32 fixup + re-scan of flagged lanes
    fixup_scan<<<dim3(B_DIM, FIX_SLICES), 256>>>(x, W1, cnt, list, sp);

    // GEMM2 (tf32): out = spikes @ W2^T
    gemm_tf32_mma<<<grid, NT_GEMM, SMEM_DYN>>>(sp, w2t, out);
}

// round 10
// speedup vs baseline: 1.2921x; 1.0303x over previous
#include <cuda_runtime.h>
#include <cstdint>

// Problem dims (fixed by the dataset)
#define T_DIM 128
#define B_DIM 64
#define H_DIM 1024
#define M_DIM (T_DIM * B_DIM)   // 8192
#define BH    (B_DIM * H_DIM)   // 65536

// Scratch (allocation-free rule: __device__ globals)
__device__ float g_xt[(size_t)M_DIM * H_DIM];     // 32 MB  tf32-rounded x
__device__ float g_xproj[(size_t)M_DIM * H_DIM];  // 32 MB  approx x_proj
__device__ float g_spk[(size_t)M_DIM * H_DIM];    // 32 MB  spikes
__device__ float g_w1t[(size_t)H_DIM * H_DIM];    // 4 MB   tf32-rounded W1
__device__ float g_w2t[(size_t)H_DIM * H_DIM];    // 4 MB   tf32-rounded W2
__device__ int   g_cnt[B_DIM];                    // flagged count per b
__device__ int   g_list[B_DIM * H_DIM];           // flagged h list per b

#define DELTA 1e-3f

// ============================================================================
// Helpers
// ============================================================================
__device__ __forceinline__ uint32_t smem_u32(const void* p) {
    uint32_t a;
    asm("{ .reg .u64 t; cvta.to.shared.u64 t, %1; cvt.u32.u64 %0, t; }"
        : "=r"(a) : "l"(p));
    return a;
}
__device__ __forceinline__ void cp_async16(uint32_t dst, const void* src) {
    asm volatile("cp.async.cg.shared.global [%0], [%1], 16;"
                 :: "r"(dst), "l"(src) : "memory");
}
#define CP_ASYNC_COMMIT() asm volatile("cp.async.commit_group;" ::: "memory")
#define CP_ASYNC_WAIT(n)  asm volatile("cp.async.wait_group %0;" :: "n"(n) : "memory")

__device__ __forceinline__ void mma_tf32(float* d, const uint32_t* a, const uint32_t* b) {
    asm volatile(
        "mma.sync.aligned.m16n8k8.row.col.f32.tf32.tf32.f32 "
        "{%0,%1,%2,%3}, {%4,%5,%6,%7}, {%8,%9}, {%0,%1,%2,%3};"
        : "+f"(d[0]), "+f"(d[1]), "+f"(d[2]), "+f"(d[3])
        : "r"(a[0]), "r"(a[1]), "r"(a[2]), "r"(a[3]),
          "r"(b[0]), "r"(b[1]));
}

// ============================================================================
// Plain TF32 tensor-core NT-GEMM: C[M,N] = A[M,K] * B[N,K]^T (operands are
// pre-rounded tf32 values in fp32 storage).
// CTA tile 128x128, BK=32, 128 threads (4 warps: 2(M) x 2(N), 64x64 each).
// TWO CTAs per SM (96 KB smem each, <=256 regs) so one CTA's barriers /
// prologue / epilogue overlap the other's MMA stream.
// 3-stage cp.async pipeline, one __syncthreads per chunk.
// XOR-swizzled smem: float index = row*32 + (((k>>2) ^ (row&7)) << 2) + (k&3)
// ============================================================================
#define BM        128
#define BN        128
#define BKF       32
#define A_U32     (BM * BKF)               // 4096 u32 = 16 KB
#define B_U32     (BN * BKF)               // 4096 u32 = 16 KB
#define STAGE_U32 (A_U32 + B_U32)          // 8192 u32 = 32 KB
#define STAGE_BYTES (STAGE_U32 * 4)
#define NSTAGE    3
#define SMEM_DYN  (NSTAGE * STAGE_BYTES)   // 96 KB
#define NT_GEMM   128

__global__ void __launch_bounds__(NT_GEMM, 2)
gemm_tf32_mma(const float* __restrict__ A,
              const float* __restrict__ Bm,
              float* __restrict__ C)
{
    extern __shared__ float sm[];
    const uint32_t smu = smem_u32(sm);

    const int tid  = threadIdx.x;
    const int lane = tid & 31;
    const int wid  = tid >> 5;
    const int g = lane >> 2;
    const int t = lane & 3;
    const int wm = (wid >> 1) * 64;   // 2 warps over M
    const int wn = (wid & 1) * 64;    // 2 warps over N

    const int m0 = blockIdx.y * BM;
    const int n0 = blockIdx.x * BN;

    const float* Abase = A  + (size_t)m0 * H_DIM;
    const float* Bbase = Bm + (size_t)n0 * H_DIM;

    // cp.async geometry: A = 1024 f4 / 128 thr = 8; B = 1024 / 128 = 8.
    int lra[8], lqa[8];
    uint32_t sda[8];
#pragma unroll
    for (int p = 0; p < 8; p++) {
        int f = tid + p * NT_GEMM;
        lra[p] = f >> 3;
        lqa[p] = f & 7;
        sda[p] = (uint32_t)((lra[p] * 32 + ((lqa[p] ^ (lra[p] & 7)) << 2)) * 4);
    }

    float acc[4][8][4];
#pragma unroll
    for (int i = 0; i < 4; i++)
#pragma unroll
        for (int j = 0; j < 8; j++)
#pragma unroll
            for (int r = 0; r < 4; r++) acc[i][j][r] = 0.0f;

    auto prefetch = [&](int chunk, int stage) {
        const uint32_t base = smu + (uint32_t)stage * STAGE_BYTES;
#pragma unroll
        for (int p = 0; p < 8; p++)
            cp_async16(base + sda[p],
                       Abase + (size_t)lra[p] * H_DIM + chunk * BKF + lqa[p] * 4);
#pragma unroll
        for (int p = 0; p < 8; p++)
            cp_async16(base + (uint32_t)(A_U32 * 4) + sda[p],
                       Bbase + (size_t)lra[p] * H_DIM + chunk * BKF + lqa[p] * 4);
    };

    const int NCH = H_DIM / BKF;   // 32
    prefetch(0, 0);
    CP_ASYNC_COMMIT();
    prefetch(1, 1);
    CP_ASYNC_COMMIT();

    int stage = 0;
    for (int it = 0; it < NCH; ++it) {
        if (it + 1 < NCH) { CP_ASYNC_WAIT(1); } else { CP_ASYNC_WAIT(0); }
        __syncthreads();
        if (it + 2 < NCH) {
            int s2 = stage + 2; if (s2 >= NSTAGE) s2 -= NSTAGE;
            prefetch(it + 2, s2);
            CP_ASYNC_COMMIT();
        }

        const uint32_t* As = (const uint32_t*)sm + (size_t)stage * STAGE_U32;
        const uint32_t* Bs = As + A_U32;

#pragma unroll
        for (int ks = 0; ks < 4; ks++) {
            const int c0 = ((ks * 2) ^ g) << 2;
            const int c1 = ((ks * 2 + 1) ^ g) << 2;

            uint32_t af[4][4];
#pragma unroll
            for (int mt = 0; mt < 4; mt++) {
                const int mb = wm + mt * 16 + g;
                af[mt][0] = As[mb * 32 + c0 + t];
                af[mt][1] = As[(mb + 8) * 32 + c0 + t];
                af[mt][2] = As[mb * 32 + c1 + t];
                af[mt][3] = As[(mb + 8) * 32 + c1 + t];
            }
            uint32_t bf[8][2];
#pragma unroll
            for (int nt = 0; nt < 8; nt++) {
                const int nb = wn + nt * 8 + g;
                bf[nt][0] = Bs[nb * 32 + c0 + t];
                bf[nt][1] = Bs[nb * 32 + c1 + t];
            }
#pragma unroll
            for (int mt = 0; mt < 4; mt++)
#pragma unroll
                for (int nt = 0; nt < 8; nt++)
                    mma_tf32(acc[mt][nt], af[mt], bf[nt]);
        }

        if (++stage >= NSTAGE) stage = 0;
    }

    // Epilogue: direct STG (float2 pairs; fragment cols 2t, 2t+1 contiguous)
#pragma unroll
    for (int mt = 0; mt < 4; mt++) {
#pragma unroll
        for (int nt = 0; nt < 8; nt++) {
            const int row = m0 + wm + mt * 16 + g;
            const int col = n0 + wn + nt * 8 + 2 * t;
            float2 v01 = make_float2(acc[mt][nt][0], acc[mt][nt][1]);
            float2 v23 = make_float2(acc[mt][nt][2], acc[mt][nt][3]);
            *(float2*)&C[(size_t)row * H_DIM + col] = v01;
            *(float2*)&C[(size_t)(row + 8) * H_DIM + col] = v23;
        }
    }
}

// ----------------------------------------------------------------------------
// Round fp32 array to TF32 values (rna), float4 per thread, streaming.
// Also zeroes the flag counters from block 0 (saves a memset launch).
// ----------------------------------------------------------------------------
__global__ void __launch_bounds__(256)
round_tf32(const float* __restrict__ src, float* __restrict__ dst,
           int* __restrict__ cnt_to_zero)
{
    if (cnt_to_zero && blockIdx.x == 0 && threadIdx.x < B_DIM)
        cnt_to_zero[threadIdx.x] = 0;

    int i = (blockIdx.x * blockDim.x + threadIdx.x) * 4;
    float4 v = *(const float4*)(src + i);
    uint32_t o0, o1, o2, o3;
    asm("cvt.rna.tf32.f32 %0, %1;" : "=r"(o0) : "f"(v.x));
    asm("cvt.rna.tf32.f32 %0, %1;" : "=r"(o1) : "f"(v.y));
    asm("cvt.rna.tf32.f32 %0, %1;" : "=r"(o2) : "f"(v.z));
    asm("cvt.rna.tf32.f32 %0, %1;" : "=r"(o3) : "f"(v.w));
    float4 r;
    r.x = __uint_as_float(o0); r.y = __uint_as_float(o1);
    r.z = __uint_as_float(o2); r.w = __uint_as_float(o3);
    *(float4*)(dst + i) = r;
}

// ----------------------------------------------------------------------------
// LIF scan over approx x_proj + flag threshold-marginal lanes.
// ----------------------------------------------------------------------------
__global__ void __launch_bounds__(256)
scan_flag(const float* __restrict__ xp, float* __restrict__ spk,
          int* __restrict__ cnt, int* __restrict__ list)
{
    const int idx = blockIdx.x * blockDim.x + threadIdx.x;
    if (idx >= BH) return;

    float v = 0.0f;
    bool flag = false;
    #pragma unroll 8
    for (int t = 0; t < T_DIM; t++) {
        const float x = xp[(size_t)t * BH + idx];
        const float h = v + (x - v) * 0.5f;
        flag |= (fabsf(h - 1.0f) < DELTA);
        const bool fire = (h >= 1.0f);
        spk[(size_t)t * BH + idx] = fire ? 1.0f : 0.0f;
        v = fire ? 0.0f : h;
    }
    if (flag) {
        const int b = idx >> 10;
        const int h = idx & 1023;
        int p = atomicAdd(&cnt[b], 1);
        list[(b << 10) + p] = h;
    }
}

// ----------------------------------------------------------------------------
// Fixup: recompute x_proj for flagged lanes in EXACT sequential fp32, rerun
// LIF, overwrite spikes. Grid (B_DIM, FIX_SLICES).
// Warps partition T; lane map jg = lane&7 (j = jg*4+jj), tg = lane>>3.
// ----------------------------------------------------------------------------
#define FIX_SLICES 2

__global__ void __launch_bounds__(256)
fixup_scan(const float* __restrict__ x,   // original fp32 x [T,B,H]
           const float* __restrict__ W1,  // original fp32 W1 [H,H]
           const int* __restrict__ cnt,
           const int* __restrict__ list,
           float* __restrict__ spk)
{
    __shared__ float Xs[128 * 65];   // 33280 B
    __shared__ float Ws[32 * 65];    //  8320 B
    __shared__ int   hlist[32];

    const int b     = blockIdx.x;
    const int slice = blockIdx.y;
    const int tid   = threadIdx.x;
    const int lane  = tid & 31;
    const int w     = tid >> 5;
    const int jg    = lane & 7;
    const int tg    = lane >> 3;
    const int tbase = w * 16 + tg * 4;
    const int n     = cnt[b];

    for (int base = slice * 32; base < n; base += FIX_SLICES * 32) {
        const int nh = min(32, n - base);

        if (tid < 32)
            hlist[tid] = (base + tid < n) ? list[(b << 10) + base + tid] : 0;
        __syncthreads();

        float acc[4][4];   // [jj][tt]
#pragma unroll
        for (int jj = 0; jj < 4; jj++)
#pragma unroll
            for (int tt = 0; tt < 4; tt++) acc[jj][tt] = 0.0f;

        for (int kc = 0; kc < 16; kc++) {
#pragma unroll
            for (int p = 0; p < 8; p++) {
                int f = tid + p * 256;
                int tt_ = f >> 4, c4 = f & 15;
                float4 v = *(const float4*)(x + (size_t)tt_ * BH + (b << 10) + kc * 64 + c4 * 4);
                float* d = &Xs[tt_ * 65 + c4 * 4];
                d[0] = v.x; d[1] = v.y; d[2] = v.z; d[3] = v.w;
            }
#pragma unroll
            for (int p = 0; p < 8; p++) {
                int f = tid + p * 256;
                int j = f >> 6, k = f & 63;
                Ws[j * 65 + k] = W1[(size_t)hlist[j] * H_DIM + kc * 64 + k];
            }
            __syncthreads();

            for (int k = 0; k < 64; k++) {
                float wv[4], xv[4];
#pragma unroll
                for (int jj = 0; jj < 4; jj++) wv[jj] = Ws[(jg * 4 + jj) * 65 + k];
#pragma unroll
                for (int tt = 0; tt < 4; tt++) xv[tt] = Xs[(tbase + tt) * 65 + k];
#pragma unroll
                for (int jj = 0; jj < 4; jj++)
#pragma unroll
                    for (int tt = 0; tt < 4; tt++)
                        acc[jj][tt] = fmaf(wv[jj], xv[tt], acc[jj][tt]);
            }
            __syncthreads();
        }

        float* xcol = Xs;
#pragma unroll
        for (int jj = 0; jj < 4; jj++)
#pragma unroll
            for (int tt = 0; tt < 4; tt++)
                xcol[(jg * 4 + jj) * 129 + tbase + tt] = acc[jj][tt];
        __syncthreads();

        if (tid < nh) {
            const int h = hlist[tid];
            float v = 0.0f;
            for (int t = 0; t < T_DIM; t++) {
                const float xc = xcol[tid * 129 + t];
                const float hm = v + (xc - v) * 0.5f;
                const bool fire = (hm >= 1.0f);
                spk[(size_t)t * BH + (b << 10) + h] = fire ? 1.0f : 0.0f;
                v = fire ? 0.0f : hm;
            }
        }
        __syncthreads();
    }
}

// ----------------------------------------------------------------------------
// Launch
// ----------------------------------------------------------------------------
extern "C" void kernel_launch(void* const* d_in, const int* in_sizes, int n_in,
                              void* d_out, int out_size)
{
    const float* x  = (const float*)d_in[0];  // [T,B,H]
    const float* W1 = (const float*)d_in[1];  // [H,H]
    const float* W2 = (const float*)d_in[2];  // [H,H]
    float* out = (float*)d_out;               // [T,B,H]

    float *xt, *xp, *sp, *w1t, *w2t;
    int *cnt, *list;
    cudaGetSymbolAddress((void**)&xt, g_xt);
    cudaGetSymbolAddress((void**)&xp, g_xproj);
    cudaGetSymbolAddress((void**)&sp, g_spk);
    cudaGetSymbolAddress((void**)&w1t, g_w1t);
    cudaGetSymbolAddress((void**)&w2t, g_w2t);
    cudaGetSymbolAddress((void**)&cnt, g_cnt);
    cudaGetSymbolAddress((void**)&list, g_list);

    cudaFuncSetAttribute(gemm_tf32_mma,
                         cudaFuncAttributeMaxDynamicSharedMemorySize, SMEM_DYN);

    // Pre-round operands to tf32 values (rna, unbiased). Spikes are exactly
    // representable so GEMM2 needs only W2 rounded. First round also zeroes cnt.
    round_tf32<<<(M_DIM * H_DIM) / (256 * 4), 256>>>(x, xt, cnt);
    round_tf32<<<(H_DIM * H_DIM) / (256 * 4), 256>>>(W1, w1t, nullptr);
    round_tf32<<<(H_DIM * H_DIM) / (256 * 4), 256>>>(W2, w2t, nullptr);

    dim3 grid(H_DIM / BN, M_DIM / BM);  // (8, 64)

    // GEMM1 approx (tf32): x_proj ~= x @ W1^T
    gemm_tf32_mma<<<grid, NT_GEMM, SMEM_DYN>>>(xt, w1t, xp);

    // LIF scan + flag marginal lanes
    scan_flag<<<BH / 256, 256>>>(xp, sp, cnt, list);

    // Exact fp32 fixup + re-scan of flagged lanes
    fixup_scan<<<dim3(B_DIM, FIX_SLICES), 256>>>(x, W1, cnt, list, sp);

    // GEMM2 (tf32): out = spikes @ W2^T
    gemm_tf32_mma<<<grid, NT_GEMM, SMEM_DYN>>>(sp, w2t, out);
}

// round 11
// speedup vs baseline: 1.3257x; 1.0260x over previous
#include <cuda_runtime.h>
#include <cstdint>

// Problem dims (fixed by the dataset)
#define T_DIM 128
#define B_DIM 64
#define H_DIM 1024
#define M_DIM (T_DIM * B_DIM)   // 8192
#define BH    (B_DIM * H_DIM)   // 65536

// Scratch (allocation-free rule: __device__ globals)
__device__ float g_xt[(size_t)M_DIM * H_DIM];     // 32 MB  tf32-rounded x
__device__ float g_xproj[(size_t)M_DIM * H_DIM];  // 32 MB  approx x_proj
__device__ float g_spk[(size_t)M_DIM * H_DIM];    // 32 MB  spikes
__device__ float g_w1t[(size_t)H_DIM * H_DIM];    // 4 MB   tf32-rounded W1
__device__ float g_w2t[(size_t)H_DIM * H_DIM];    // 4 MB   tf32-rounded W2
__device__ int   g_cnt[B_DIM];                    // flagged count per b
__device__ int   g_list[B_DIM * H_DIM];           // flagged h list per b

#define DELTA 1e-3f

// ============================================================================
// Helpers
// ============================================================================
__device__ __forceinline__ uint32_t smem_u32(const void* p) {
    uint32_t a;
    asm("{ .reg .u64 t; cvta.to.shared.u64 t, %1; cvt.u32.u64 %0, t; }"
        : "=r"(a) : "l"(p));
    return a;
}
__device__ __forceinline__ void cp_async16(uint32_t dst, const void* src) {
    asm volatile("cp.async.cg.shared.global [%0], [%1], 16;"
                 :: "r"(dst), "l"(src) : "memory");
}
#define CP_ASYNC_COMMIT() asm volatile("cp.async.commit_group;" ::: "memory")
#define CP_ASYNC_WAIT(n)  asm volatile("cp.async.wait_group %0;" :: "n"(n) : "memory")

__device__ __forceinline__ void mma_tf32(float* d, const uint32_t* a, const uint32_t* b) {
    asm volatile(
        "mma.sync.aligned.m16n8k8.row.col.f32.tf32.tf32.f32 "
        "{%0,%1,%2,%3}, {%4,%5,%6,%7}, {%8,%9}, {%0,%1,%2,%3};"
        : "+f"(d[0]), "+f"(d[1]), "+f"(d[2]), "+f"(d[3])
        : "r"(a[0]), "r"(a[1]), "r"(a[2]), "r"(a[3]),
          "r"(b[0]), "r"(b[1]));
}

// ============================================================================
// Plain TF32 tensor-core NT-GEMM: C[M,N] = A[M,K] * B[N,K]^T (operands are
// pre-rounded tf32 values in fp32 storage).
// CTA tile 128x128, BK=32, 128 threads (4 warps: 2(M) x 2(N), 64x64 each).
// TWO CTAs per SM; 3-stage cp.async pipeline, one __syncthreads per chunk.
// XOR-swizzled smem: float index = row*32 + (((k>>2) ^ (row&7)) << 2) + (k&3)
// ============================================================================
#define BM        128
#define BN        128
#define BKF       32
#define A_U32     (BM * BKF)               // 4096 u32 = 16 KB
#define B_U32     (BN * BKF)               // 4096 u32 = 16 KB
#define STAGE_U32 (A_U32 + B_U32)          // 8192 u32 = 32 KB
#define STAGE_BYTES (STAGE_U32 * 4)
#define NSTAGE    3
#define SMEM_DYN  (NSTAGE * STAGE_BYTES)   // 96 KB
#define NT_GEMM   128

__global__ void __launch_bounds__(NT_GEMM, 2)
gemm_tf32_mma(const float* __restrict__ A,
              const float* __restrict__ Bm,
              float* __restrict__ C)
{
    extern __shared__ float sm[];
    const uint32_t smu = smem_u32(sm);

    const int tid  = threadIdx.x;
    const int lane = tid & 31;
    const int wid  = tid >> 5;
    const int g = lane >> 2;
    const int t = lane & 3;
    const int wm = (wid >> 1) * 64;   // 2 warps over M
    const int wn = (wid & 1) * 64;    // 2 warps over N

    const int m0 = blockIdx.y * BM;
    const int n0 = blockIdx.x * BN;

    const float* Abase = A  + (size_t)m0 * H_DIM;
    const float* Bbase = Bm + (size_t)n0 * H_DIM;

    // cp.async geometry: A = 1024 f4 / 128 thr = 8; B = 1024 / 128 = 8.
    int lra[8], lqa[8];
    uint32_t sda[8];
#pragma unroll
    for (int p = 0; p < 8; p++) {
        int f = tid + p * NT_GEMM;
        lra[p] = f >> 3;
        lqa[p] = f & 7;
        sda[p] = (uint32_t)((lra[p] * 32 + ((lqa[p] ^ (lra[p] & 7)) << 2)) * 4);
    }

    float acc[4][8][4];
#pragma unroll
    for (int i = 0; i < 4; i++)
#pragma unroll
        for (int j = 0; j < 8; j++)
#pragma unroll
            for (int r = 0; r < 4; r++) acc[i][j][r] = 0.0f;

    auto prefetch = [&](int chunk, int stage) {
        const uint32_t base = smu + (uint32_t)stage * STAGE_BYTES;
#pragma unroll
        for (int p = 0; p < 8; p++)
            cp_async16(base + sda[p],
                       Abase + (size_t)lra[p] * H_DIM + chunk * BKF + lqa[p] * 4);
#pragma unroll
        for (int p = 0; p < 8; p++)
            cp_async16(base + (uint32_t)(A_U32 * 4) + sda[p],
                       Bbase + (size_t)lra[p] * H_DIM + chunk * BKF + lqa[p] * 4);
    };

    const int NCH = H_DIM / BKF;   // 32
    prefetch(0, 0);
    CP_ASYNC_COMMIT();
    prefetch(1, 1);
    CP_ASYNC_COMMIT();

    int stage = 0;
    for (int it = 0; it < NCH; ++it) {
        if (it + 1 < NCH) { CP_ASYNC_WAIT(1); } else { CP_ASYNC_WAIT(0); }
        __syncthreads();
        if (it + 2 < NCH) {
            int s2 = stage + 2; if (s2 >= NSTAGE) s2 -= NSTAGE;
            prefetch(it + 2, s2);
            CP_ASYNC_COMMIT();
        }

        const uint32_t* As = (const uint32_t*)sm + (size_t)stage * STAGE_U32;
        const uint32_t* Bs = As + A_U32;

#pragma unroll
        for (int ks = 0; ks < 4; ks++) {
            const int c0 = ((ks * 2) ^ g) << 2;
            const int c1 = ((ks * 2 + 1) ^ g) << 2;

            uint32_t af[4][4];
#pragma unroll
            for (int mt = 0; mt < 4; mt++) {
                const int mb = wm + mt * 16 + g;
                af[mt][0] = As[mb * 32 + c0 + t];
                af[mt][1] = As[(mb + 8) * 32 + c0 + t];
                af[mt][2] = As[mb * 32 + c1 + t];
                af[mt][3] = As[(mb + 8) * 32 + c1 + t];
            }
            uint32_t bf[8][2];
#pragma unroll
            for (int nt = 0; nt < 8; nt++) {
                const int nb = wn + nt * 8 + g;
                bf[nt][0] = Bs[nb * 32 + c0 + t];
                bf[nt][1] = Bs[nb * 32 + c1 + t];
            }
#pragma unroll
            for (int mt = 0; mt < 4; mt++)
#pragma unroll
                for (int nt = 0; nt < 8; nt++)
                    mma_tf32(acc[mt][nt], af[mt], bf[nt]);
        }

        if (++stage >= NSTAGE) stage = 0;
    }

    // Epilogue: direct STG (float2 pairs; fragment cols 2t, 2t+1 contiguous)
#pragma unroll
    for (int mt = 0; mt < 4; mt++) {
#pragma unroll
        for (int nt = 0; nt < 8; nt++) {
            const int row = m0 + wm + mt * 16 + g;
            const int col = n0 + wn + nt * 8 + 2 * t;
            float2 v01 = make_float2(acc[mt][nt][0], acc[mt][nt][1]);
            float2 v23 = make_float2(acc[mt][nt][2], acc[mt][nt][3]);
            *(float2*)&C[(size_t)row * H_DIM + col] = v01;
            *(float2*)&C[(size_t)(row + 8) * H_DIM + col] = v23;
        }
    }
}

// ----------------------------------------------------------------------------
// Fused round pass: one grid rounds x (2M float4), W1 (256K f4), W2 (256K f4)
// to tf32 values (rna). Block 0 also zeroes the flag counters.
// ----------------------------------------------------------------------------
#define XF4   (M_DIM * H_DIM / 4)          // 2097152
#define WF4   (H_DIM * H_DIM / 4)          //  262144
#define RND_BLOCKS ((XF4 + 2 * WF4) / 256) // 10240

__global__ void __launch_bounds__(256)
round_all(const float* __restrict__ x,  float* __restrict__ xt,
          const float* __restrict__ W1, float* __restrict__ w1t,
          const float* __restrict__ W2, float* __restrict__ w2t,
          int* __restrict__ cnt)
{
    if (blockIdx.x == 0 && threadIdx.x < B_DIM)
        cnt[threadIdx.x] = 0;

    int gid = blockIdx.x * blockDim.x + threadIdx.x;   // float4 index
    const float* src;
    float* dst;
    int i;
    if (gid < XF4)            { src = x;  dst = xt;  i = gid; }
    else if (gid < XF4 + WF4) { src = W1; dst = w1t; i = gid - XF4; }
    else                      { src = W2; dst = w2t; i = gid - XF4 - WF4; }

    float4 v = *(const float4*)(src + (size_t)i * 4);
    uint32_t o0, o1, o2, o3;
    asm("cvt.rna.tf32.f32 %0, %1;" : "=r"(o0) : "f"(v.x));
    asm("cvt.rna.tf32.f32 %0, %1;" : "=r"(o1) : "f"(v.y));
    asm("cvt.rna.tf32.f32 %0, %1;" : "=r"(o2) : "f"(v.z));
    asm("cvt.rna.tf32.f32 %0, %1;" : "=r"(o3) : "f"(v.w));
    float4 r;
    r.x = __uint_as_float(o0); r.y = __uint_as_float(o1);
    r.z = __uint_as_float(o2); r.w = __uint_as_float(o3);
    *(float4*)(dst + (size_t)i * 4) = r;
}

// ----------------------------------------------------------------------------
// LIF scan over approx x_proj + flag threshold-marginal lanes.
// ----------------------------------------------------------------------------
__global__ void __launch_bounds__(256)
scan_flag(const float* __restrict__ xp, float* __restrict__ spk,
          int* __restrict__ cnt, int* __restrict__ list)
{
    const int idx = blockIdx.x * blockDim.x + threadIdx.x;
    if (idx >= BH) return;

    float v = 0.0f;
    bool flag = false;
    #pragma unroll 8
    for (int t = 0; t < T_DIM; t++) {
        const float x = xp[(size_t)t * BH + idx];
        const float h = v + (x - v) * 0.5f;
        flag |= (fabsf(h - 1.0f) < DELTA);
        const bool fire = (h >= 1.0f);
        spk[(size_t)t * BH + idx] = fire ? 1.0f : 0.0f;
        v = fire ? 0.0f : h;
    }
    if (flag) {
        const int b = idx >> 10;
        const int h = idx & 1023;
        int p = atomicAdd(&cnt[b], 1);
        list[(b << 10) + p] = h;
    }
}

// ----------------------------------------------------------------------------
// Fixup: recompute x_proj for flagged lanes in EXACT sequential fp32, rerun
// LIF, overwrite spikes. Grid (B_DIM, FIX_SLICES) — FIX_SLICES=4 so the
// typical ~113 flagged lanes/b (4 batches of 32) spread one batch per slice:
// wall-time = ONE batch instead of two.
// Warps partition T; lane map jg = lane&7 (j = jg*4+jj), tg = lane>>3.
// ----------------------------------------------------------------------------
#define FIX_SLICES 4

__global__ void __launch_bounds__(256)
fixup_scan(const float* __restrict__ x,   // original fp32 x [T,B,H]
           const float* __restrict__ W1,  // original fp32 W1 [H,H]
           const int* __restrict__ cnt,
           const int* __restrict__ list,
           float* __restrict__ spk)
{
    __shared__ float Xs[128 * 65];   // 33280 B
    __shared__ float Ws[32 * 65];    //  8320 B
    __shared__ int   hlist[32];

    const int b     = blockIdx.x;
    const int slice = blockIdx.y;
    const int tid   = threadIdx.x;
    const int lane  = tid & 31;
    const int w     = tid >> 5;
    const int jg    = lane & 7;
    const int tg    = lane >> 3;
    const int tbase = w * 16 + tg * 4;
    const int n     = cnt[b];

    for (int base = slice * 32; base < n; base += FIX_SLICES * 32) {
        const int nh = min(32, n - base);

        if (tid < 32)
            hlist[tid] = (base + tid < n) ? list[(b << 10) + base + tid] : 0;
        __syncthreads();

        float acc[4][4];   // [jj][tt]
#pragma unroll
        for (int jj = 0; jj < 4; jj++)
#pragma unroll
            for (int tt = 0; tt < 4; tt++) acc[jj][tt] = 0.0f;

        for (int kc = 0; kc < 16; kc++) {
#pragma unroll
            for (int p = 0; p < 8; p++) {
                int f = tid + p * 256;
                int tt_ = f >> 4, c4 = f & 15;
                float4 v = *(const float4*)(x + (size_t)tt_ * BH + (b << 10) + kc * 64 + c4 * 4);
                float* d = &Xs[tt_ * 65 + c4 * 4];
                d[0] = v.x; d[1] = v.y; d[2] = v.z; d[3] = v.w;
            }
#pragma unroll
            for (int p = 0; p < 8; p++) {
                int f = tid + p * 256;
                int j = f >> 6, k = f & 63;
                Ws[j * 65 + k] = W1[(size_t)hlist[j] * H_DIM + kc * 64 + k];
            }
            __syncthreads();

            for (int k = 0; k < 64; k++) {
                float wv[4], xv[4];
#pragma unroll
                for (int jj = 0; jj < 4; jj++) wv[jj] = Ws[(jg * 4 + jj) * 65 + k];
#pragma unroll
                for (int tt = 0; tt < 4; tt++) xv[tt] = Xs[(tbase + tt) * 65 + k];
#pragma unroll
                for (int jj = 0; jj < 4; jj++)
#pragma unroll
                    for (int tt = 0; tt < 4; tt++)
                        acc[jj][tt] = fmaf(wv[jj], xv[tt], acc[jj][tt]);
            }
            __syncthreads();
        }

        float* xcol = Xs;
#pragma unroll
        for (int jj = 0; jj < 4; jj++)
#pragma unroll
            for (int tt = 0; tt < 4; tt++)
                xcol[(jg * 4 + jj) * 129 + tbase + tt] = acc[jj][tt];
        __syncthreads();

        if (tid < nh) {
            const int h = hlist[tid];
            float v = 0.0f;
            for (int t = 0; t < T_DIM; t++) {
                const float xc = xcol[tid * 129 + t];
                const float hm = v + (xc - v) * 0.5f;
                const bool fire = (hm >= 1.0f);
                spk[(size_t)t * BH + (b << 10) + h] = fire ? 1.0f : 0.0f;
                v = fire ? 0.0f : hm;
            }
        }
        __syncthreads();
    }
}

// ----------------------------------------------------------------------------
// Launch
// ----------------------------------------------------------------------------
extern "C" void kernel_launch(void* const* d_in, const int* in_sizes, int n_in,
                              void* d_out, int out_size)
{
    const float* x  = (const float*)d_in[0];  // [T,B,H]
    const float* W1 = (const float*)d_in[1];  // [H,H]
    const float* W2 = (const float*)d_in[2];  // [H,H]
    float* out = (float*)d_out;               // [T,B,H]

    float *xt, *xp, *sp, *w1t, *w2t;
    int *cnt, *list;
    cudaGetSymbolAddress((void**)&xt, g_xt);
    cudaGetSymbolAddress((void**)&xp, g_xproj);
    cudaGetSymbolAddress((void**)&sp, g_spk);
    cudaGetSymbolAddress((void**)&w1t, g_w1t);
    cudaGetSymbolAddress((void**)&w2t, g_w2t);
    cudaGetSymbolAddress((void**)&cnt, g_cnt);
    cudaGetSymbolAddress((void**)&list, g_list);

    cudaFuncSetAttribute(gemm_tf32_mma,
                         cudaFuncAttributeMaxDynamicSharedMemorySize, SMEM_DYN);

    // Fused tf32 pre-round of x, W1, W2 (rna, unbiased) + cnt zeroing.
    round_all<<<RND_BLOCKS, 256>>>(x, xt, W1, w1t, W2, w2t, cnt);

    dim3 grid(H_DIM / BN, M_DIM / BM);  // (8, 64)

    // GEMM1 approx (tf32): x_proj ~= x @ W1^T
    gemm_tf32_mma<<<grid, NT_GEMM, SMEM_DYN>>>(xt, w1t, xp);

    // LIF scan + flag marginal lanes
    scan_flag<<<BH / 256, 256>>>(xp, sp, cnt, list);

    // Exact fp32 fixup + re-scan of flagged lanes
    fixup_scan<<<dim3(B_DIM, FIX_SLICES), 256>>>(x, W1, cnt, list, sp);

    // GEMM2 (tf32): out = spikes @ W2^T
    gemm_tf32_mma<<<grid, NT_GEMM, SMEM_DYN>>>(sp, w2t, out);
}

// round 12
// speedup vs baseline: 1.5278x; 1.1524x over previous
#include <cuda_runtime.h>
#include <cstdint>

// Problem dims (fixed by the dataset)
#define T_DIM 128
#define B_DIM 64
#define H_DIM 1024
#define M_DIM (T_DIM * B_DIM)   // 8192
#define BH    (B_DIM * H_DIM)   // 65536

// Scratch (allocation-free rule: __device__ globals)
__device__ float g_xfix[(size_t)B_DIM * 1024 * T_DIM]; // 32 MB exact xcol per flagged slot
__device__ float g_xproj[(size_t)M_DIM * H_DIM];       // 32 MB approx x_proj
__device__ float g_spk[(size_t)M_DIM * H_DIM];         // 32 MB spikes
__device__ float g_w1t[(size_t)H_DIM * H_DIM];         // 4 MB tf32-rounded W1
__device__ float g_w2t[(size_t)H_DIM * H_DIM];         // 4 MB tf32-rounded W2
__device__ int   g_cnt[B_DIM];
__device__ int   g_list[B_DIM * H_DIM];

#define DELTA 1e-3f

// ============================================================================
// Helpers
// ============================================================================
__device__ __forceinline__ uint32_t smem_u32(const void* p) {
    uint32_t a;
    asm("{ .reg .u64 t; cvta.to.shared.u64 t, %1; cvt.u32.u64 %0, t; }"
        : "=r"(a) : "l"(p));
    return a;
}
__device__ __forceinline__ void cp_async16(uint32_t dst, const void* src) {
    asm volatile("cp.async.cg.shared.global [%0], [%1], 16;"
                 :: "r"(dst), "l"(src) : "memory");
}
#define CP_ASYNC_COMMIT() asm volatile("cp.async.commit_group;" ::: "memory")
#define CP_ASYNC_WAIT(n)  asm volatile("cp.async.wait_group %0;" :: "n"(n) : "memory")

__device__ __forceinline__ void mma_tf32(float* d, const uint32_t* a, const uint32_t* b) {
    asm volatile(
        "mma.sync.aligned.m16n8k8.row.col.f32.tf32.tf32.f32 "
        "{%0,%1,%2,%3}, {%4,%5,%6,%7}, {%8,%9}, {%0,%1,%2,%3};"
        : "+f"(d[0]), "+f"(d[1]), "+f"(d[2]), "+f"(d[3])
        : "r"(a[0]), "r"(a[1]), "r"(a[2]), "r"(a[3]),
          "r"(b[0]), "r"(b[1]));
}

// ============================================================================
// TF32 tensor-core NT-GEMM (unchanged from R10 best): C = A * B^T.
// CTA 128x128, BK=32, 128 threads, 2 CTAs/SM, 3-stage cp.async.
// A may be raw fp32 (HW truncates to tf32); B should be pre-rounded.
// ============================================================================
#define BM        128
#define BN        128
#define BKF       32
#define A_U32     (BM * BKF)
#define B_U32     (BN * BKF)
#define STAGE_U32 (A_U32 + B_U32)
#define STAGE_BYTES (STAGE_U32 * 4)
#define NSTAGE    3
#define SMEM_DYN  (NSTAGE * STAGE_BYTES)   // 96 KB
#define NT_GEMM   128

__global__ void __launch_bounds__(NT_GEMM, 2)
gemm_tf32_mma(const float* __restrict__ A,
              const float* __restrict__ Bm,
              float* __restrict__ C)
{
    extern __shared__ float sm[];
    const uint32_t smu = smem_u32(sm);

    const int tid  = threadIdx.x;
    const int lane = tid & 31;
    const int wid  = tid >> 5;
    const int g = lane >> 2;
    const int t = lane & 3;
    const int wm = (wid >> 1) * 64;
    const int wn = (wid & 1) * 64;

    const int m0 = blockIdx.y * BM;
    const int n0 = blockIdx.x * BN;

    const float* Abase = A  + (size_t)m0 * H_DIM;
    const float* Bbase = Bm + (size_t)n0 * H_DIM;

    int lra[8], lqa[8];
    uint32_t sda[8];
#pragma unroll
    for (int p = 0; p < 8; p++) {
        int f = tid + p * NT_GEMM;
        lra[p] = f >> 3;
        lqa[p] = f & 7;
        sda[p] = (uint32_t)((lra[p] * 32 + ((lqa[p] ^ (lra[p] & 7)) << 2)) * 4);
    }

    float acc[4][8][4];
#pragma unroll
    for (int i = 0; i < 4; i++)
#pragma unroll
        for (int j = 0; j < 8; j++)
#pragma unroll
            for (int r = 0; r < 4; r++) acc[i][j][r] = 0.0f;

    auto prefetch = [&](int chunk, int stage) {
        const uint32_t base = smu + (uint32_t)stage * STAGE_BYTES;
#pragma unroll
        for (int p = 0; p < 8; p++)
            cp_async16(base + sda[p],
                       Abase + (size_t)lra[p] * H_DIM + chunk * BKF + lqa[p] * 4);
#pragma unroll
        for (int p = 0; p < 8; p++)
            cp_async16(base + (uint32_t)(A_U32 * 4) + sda[p],
                       Bbase + (size_t)lra[p] * H_DIM + chunk * BKF + lqa[p] * 4);
    };

    const int NCH = H_DIM / BKF;
    prefetch(0, 0);
    CP_ASYNC_COMMIT();
    prefetch(1, 1);
    CP_ASYNC_COMMIT();

    int stage = 0;
    for (int it = 0; it < NCH; ++it) {
        if (it + 1 < NCH) { CP_ASYNC_WAIT(1); } else { CP_ASYNC_WAIT(0); }
        __syncthreads();
        if (it + 2 < NCH) {
            int s2 = stage + 2; if (s2 >= NSTAGE) s2 -= NSTAGE;
            prefetch(it + 2, s2);
            CP_ASYNC_COMMIT();
        }

        const uint32_t* As = (const uint32_t*)sm + (size_t)stage * STAGE_U32;
        const uint32_t* Bs = As + A_U32;

#pragma unroll
        for (int ks = 0; ks < 4; ks++) {
            const int c0 = ((ks * 2) ^ g) << 2;
            const int c1 = ((ks * 2 + 1) ^ g) << 2;

            uint32_t af[4][4];
#pragma unroll
            for (int mt = 0; mt < 4; mt++) {
                const int mb = wm + mt * 16 + g;
                af[mt][0] = As[mb * 32 + c0 + t];
                af[mt][1] = As[(mb + 8) * 32 + c0 + t];
                af[mt][2] = As[mb * 32 + c1 + t];
                af[mt][3] = As[(mb + 8) * 32 + c1 + t];
            }
            uint32_t bf[8][2];
#pragma unroll
            for (int nt = 0; nt < 8; nt++) {
                const int nb = wn + nt * 8 + g;
                bf[nt][0] = Bs[nb * 32 + c0 + t];
                bf[nt][1] = Bs[nb * 32 + c1 + t];
            }
#pragma unroll
            for (int mt = 0; mt < 4; mt++)
#pragma unroll
                for (int nt = 0; nt < 8; nt++)
                    mma_tf32(acc[mt][nt], af[mt], bf[nt]);
        }

        if (++stage >= NSTAGE) stage = 0;
    }

#pragma unroll
    for (int mt = 0; mt < 4; mt++) {
#pragma unroll
        for (int nt = 0; nt < 8; nt++) {
            const int row = m0 + wm + mt * 16 + g;
            const int col = n0 + wn + nt * 8 + 2 * t;
            float2 v01 = make_float2(acc[mt][nt][0], acc[mt][nt][1]);
            float2 v23 = make_float2(acc[mt][nt][2], acc[mt][nt][3]);
            *(float2*)&C[(size_t)row * H_DIM + col] = v01;
            *(float2*)&C[(size_t)(row + 8) * H_DIM + col] = v23;
        }
    }
}

// ----------------------------------------------------------------------------
// Round W1+W2 to tf32 (rna) + zero flag counters. 8 MB total -> ~2 us.
// ----------------------------------------------------------------------------
#define WF4   (H_DIM * H_DIM / 4)          // 262144

__global__ void __launch_bounds__(256)
round_w(const float* __restrict__ W1, float* __restrict__ w1t,
        const float* __restrict__ W2, float* __restrict__ w2t,
        int* __restrict__ cnt)
{
    if (blockIdx.x == 0 && threadIdx.x < B_DIM)
        cnt[threadIdx.x] = 0;

    int gid = blockIdx.x * blockDim.x + threadIdx.x;
    const float* src = (gid < WF4) ? W1 : W2;
    float* dst = (gid < WF4) ? w1t : w2t;
    int i = (gid < WF4) ? gid : gid - WF4;

    float4 v = *(const float4*)(src + (size_t)i * 4);
    uint32_t o0, o1, o2, o3;
    asm("cvt.rna.tf32.f32 %0, %1;" : "=r"(o0) : "f"(v.x));
    asm("cvt.rna.tf32.f32 %0, %1;" : "=r"(o1) : "f"(v.y));
    asm("cvt.rna.tf32.f32 %0, %1;" : "=r"(o2) : "f"(v.z));
    asm("cvt.rna.tf32.f32 %0, %1;" : "=r"(o3) : "f"(v.w));
    float4 r;
    r.x = __uint_as_float(o0); r.y = __uint_as_float(o1);
    r.z = __uint_as_float(o2); r.w = __uint_as_float(o3);
    *(float4*)(dst + (size_t)i * 4) = r;
}

// ----------------------------------------------------------------------------
// LIF scan over approx x_proj + flag threshold-marginal lanes.
// ----------------------------------------------------------------------------
__global__ void __launch_bounds__(256)
scan_flag(const float* __restrict__ xp, float* __restrict__ spk,
          int* __restrict__ cnt, int* __restrict__ list)
{
    const int idx = blockIdx.x * blockDim.x + threadIdx.x;
    if (idx >= BH) return;

    float v = 0.0f;
    bool flag = false;
    #pragma unroll 8
    for (int t = 0; t < T_DIM; t++) {
        const float x = xp[(size_t)t * BH + idx];
        const float h = v + (x - v) * 0.5f;
        flag |= (fabsf(h - 1.0f) < DELTA);
        const bool fire = (h >= 1.0f);
        spk[(size_t)t * BH + idx] = fire ? 1.0f : 0.0f;
        v = fire ? 0.0f : h;
    }
    if (flag) {
        const int b = idx >> 10;
        const int h = idx & 1023;
        int p = atomicAdd(&cnt[b], 1);
        list[(b << 10) + p] = h;
    }
}

// ----------------------------------------------------------------------------
// fixup_gemm: exact fp32 x_proj columns for flagged lanes -> g_xfix.
// Grid (B_DIM, 8): y&3 = h-slice (batches of 32, stride 128), y>>2 = t-half.
// CTA tile 32h x 64t, 256 threads, thread tile 2j x 4t (j = jg, jg+16).
// Smem XOR-block swizzle: row r (64 floats): phys = r*64 + ((kg ^ (r&15))<<2) + (k&3)
//   -> conflict-free float4 STS (16 distinct kq blocks per 16 lanes) and
//      conflict-free/broadcast float4 LDS in the compute loop.
// Per 4-k group per thread: 2 wv4 + 4 xv4 + 32 FMA, fully unrolled.
// ----------------------------------------------------------------------------
__global__ void __launch_bounds__(256)
fixup_gemm(const float* __restrict__ x,   // fp32 x [T,B,H]
           const float* __restrict__ W1,  // fp32 W1 [H,H]
           const int* __restrict__ cnt,
           const int* __restrict__ list,
           float* __restrict__ xfix)      // [b][slot<1024][t]
{
    __shared__ float Xs[64 * 64];   // 16 KB  (t rows, swizzled k)
    __shared__ float Ws[32 * 64];   //  8 KB  (j rows, swizzled k)
    __shared__ int   hlist[32];

    const int b   = blockIdx.x;
    const int hs  = blockIdx.y & 3;
    const int th  = blockIdx.y >> 2;      // t half (0/1)
    const int tid = threadIdx.x;
    const int jg  = tid & 15;             // j = jg, jg+16
    const int tg  = tid >> 4;             // t = 4*tg .. 4*tg+3  (local)
    const int n   = cnt[b];

    const int boff = b << 10;
    const int tglob0 = th * 64;

    for (int base = hs * 32; base < n; base += 128) {
        if (tid < 32)
            hlist[tid] = (base + tid < n) ? list[boff + base + tid] : 0;
        __syncthreads();

        float acc[2][4];
#pragma unroll
        for (int jj = 0; jj < 2; jj++)
#pragma unroll
            for (int tt = 0; tt < 4; tt++) acc[jj][tt] = 0.0f;

        for (int kc = 0; kc < 16; kc++) {
            // Stage Xs: 64 t x 64 k  (1024 float4, 4/thread, coalesced)
#pragma unroll
            for (int p = 0; p < 4; p++) {
                int f = tid + p * 256;
                int tl = f >> 4, kq = f & 15;
                float4 v = *(const float4*)(x + (size_t)(tglob0 + tl) * BH
                                            + boff + kc * 64 + kq * 4);
                *(float4*)&Xs[tl * 64 + ((kq ^ (tl & 15)) << 2)] = v;
            }
            // Stage Ws: 32 j x 64 k  (512 float4, 2/thread, coalesced)
#pragma unroll
            for (int p = 0; p < 2; p++) {
                int f = tid + p * 256;
                int j = f >> 4, kq = f & 15;
                float4 v = *(const float4*)(W1 + (size_t)hlist[j] * H_DIM
                                            + kc * 64 + kq * 4);
                *(float4*)&Ws[j * 64 + ((kq ^ (j & 15)) << 2)] = v;
            }
            __syncthreads();

            // Compute: exact fp32, k-sequential per accumulator
#pragma unroll
            for (int kg = 0; kg < 16; kg++) {
                float4 wv0 = *(const float4*)&Ws[jg * 64 + ((kg ^ (jg & 15)) << 2)];
                float4 wv1 = *(const float4*)&Ws[(jg + 16) * 64 + ((kg ^ ((jg + 16) & 15)) << 2)];
                float4 xv[4];
#pragma unroll
                for (int tt = 0; tt < 4; tt++) {
                    int r = 4 * tg + tt;
                    xv[tt] = *(const float4*)&Xs[r * 64 + ((kg ^ (r & 15)) << 2)];
                }
#pragma unroll
                for (int tt = 0; tt < 4; tt++) {
                    acc[0][tt] = fmaf(wv0.x, xv[tt].x, acc[0][tt]);
                    acc[0][tt] = fmaf(wv0.y, xv[tt].y, acc[0][tt]);
                    acc[0][tt] = fmaf(wv0.z, xv[tt].z, acc[0][tt]);
                    acc[0][tt] = fmaf(wv0.w, xv[tt].w, acc[0][tt]);
                    acc[1][tt] = fmaf(wv1.x, xv[tt].x, acc[1][tt]);
                    acc[1][tt] = fmaf(wv1.y, xv[tt].y, acc[1][tt]);
                    acc[1][tt] = fmaf(wv1.z, xv[tt].z, acc[1][tt]);
                    acc[1][tt] = fmaf(wv1.w, xv[tt].w, acc[1][tt]);
                }
            }
            __syncthreads();
        }

        // Write exact columns: xfix[b][base+j][tglob0 + 4tg .. +3]
#pragma unroll
        for (int jj = 0; jj < 2; jj++) {
            int slot = base + jg + 16 * jj;
            float4 v = make_float4(acc[jj][0], acc[jj][1], acc[jj][2], acc[jj][3]);
            *(float4*)&xfix[((size_t)(b << 10) + slot) * T_DIM + tglob0 + 4 * tg] = v;
        }
        __syncthreads();
    }
}

// ----------------------------------------------------------------------------
// fixup_lif: rerun exact LIF for flagged lanes from g_xfix, overwrite spikes.
// ----------------------------------------------------------------------------
__global__ void __launch_bounds__(256)
fixup_lif(const float* __restrict__ xfix,
          const int* __restrict__ cnt,
          const int* __restrict__ list,
          float* __restrict__ spk)
{
    const int idx = blockIdx.x * blockDim.x + threadIdx.x;  // 64*1024 lanes
    const int b = idx >> 10;
    const int slot = idx & 1023;
    if (b >= B_DIM || slot >= cnt[b]) return;

    const int h = list[(b << 10) + slot];
    const float* xc = xfix + ((size_t)(b << 10) + slot) * T_DIM;
    float v = 0.0f;
    for (int t = 0; t < T_DIM; t++) {
        const float hm = v + (xc[t] - v) * 0.5f;
        const bool fire = (hm >= 1.0f);
        spk[(size_t)t * BH + (b << 10) + h] = fire ? 1.0f : 0.0f;
        v = fire ? 0.0f : hm;
    }
}

// ----------------------------------------------------------------------------
// Launch
// ----------------------------------------------------------------------------
extern "C" void kernel_launch(void* const* d_in, const int* in_sizes, int n_in,
                              void* d_out, int out_size)
{
    const float* x  = (const float*)d_in[0];  // [T,B,H]
    const float* W1 = (const float*)d_in[1];  // [H,H]
    const float* W2 = (const float*)d_in[2];  // [H,H]
    float* out = (float*)d_out;               // [T,B,H]

    float *xf, *xp, *sp, *w1t, *w2t;
    int *cnt, *list;
    cudaGetSymbolAddress((void**)&xf, g_xfix);
    cudaGetSymbolAddress((void**)&xp, g_xproj);
    cudaGetSymbolAddress((void**)&sp, g_spk);
    cudaGetSymbolAddress((void**)&w1t, g_w1t);
    cudaGetSymbolAddress((void**)&w2t, g_w2t);
    cudaGetSymbolAddress((void**)&cnt, g_cnt);
    cudaGetSymbolAddress((void**)&list, g_list);

    cudaFuncSetAttribute(gemm_tf32_mma,
                         cudaFuncAttributeMaxDynamicSharedMemorySize, SMEM_DYN);

    // Round W1/W2 to tf32 (rna) + zero counters (x stays raw; HW RZ-truncates A).
    round_w<<<(2 * WF4) / 256, 256>>>(W1, w1t, W2, w2t, cnt);

    dim3 grid(H_DIM / BN, M_DIM / BM);  // (8, 64)

    // GEMM1 approx (tf32): x_proj ~= x @ W1^T
    gemm_tf32_mma<<<grid, NT_GEMM, SMEM_DYN>>>(x, w1t, xp);

    // LIF scan + flag marginal lanes
    scan_flag<<<BH / 256, 256>>>(xp, sp, cnt, list);

    // Exact fp32 recompute of flagged columns, then exact LIF rerun
    fixup_gemm<<<dim3(B_DIM, 8), 256>>>(x, W1, cnt, list, xf);
    fixup_lif<<<(B_DIM * 1024) / 256, 256>>>(xf, cnt, list, sp);

    // GEMM2 (tf32): out = spikes @ W2^T
    gemm_tf32_mma<<<grid, NT_GEMM, SMEM_DYN>>>(sp, w2t, out);
}